// round 3
// baseline (speedup 1.0000x reference)
#include <cuda_runtime.h>

#define NN 100000
#define NE 1600000

// ---------------- device scratch ----------------
__device__ float gP [NN*32];
__device__ float gQ [NN*32];
__device__ float gR [NN*32];
__device__ float gRW[NN*32];
__device__ float gTG[NN*32];
__device__ float gTS[NN*32];
__device__ float gWgT[1024];
__device__ float gWsT[1024];
__device__ float gMg[1024];
__device__ float gMs[1024];
__device__ int   gDeg[NN];
__device__ int   gOff[NN];
__device__ int   gOffCur[NN];
__device__ int4  gEpack[NE];   // {dst, eid, ew_bits, 0}

__device__ __forceinline__ float tanha(float x) {
    float y;
    asm("tanh.approx.f32 %0, %1;" : "=f"(y) : "f"(x));
    return y;
}

// ---------------- prep ----------------
__global__ void k_prep(const float* __restrict__ Wg, const float* __restrict__ Ws,
                       const float* __restrict__ We) {
    int t = threadIdx.x;
    int i = t >> 5, j = t & 31;
    gWgT[t] = Wg[j*32 + i];
    gWsT[t] = Ws[j*32 + i];
    float mg = 0.f, ms = 0.f;
    #pragma unroll
    for (int k = 0; k < 32; k++) {
        float we = We[k*32 + j];
        mg += Wg[k*32 + i] * we;
        ms += Ws[k*32 + i] * we;
    }
    gMg[t] = mg; gMs[t] = ms;
}

// ---------------- CSR build ----------------
__global__ __launch_bounds__(256) void k_zero_deg() {
    int i = blockIdx.x * 256 + threadIdx.x;
    if (i < NN) gDeg[i] = 0;
}

__global__ __launch_bounds__(256) void k_hist(const int* __restrict__ src) {
    int e = blockIdx.x * 256 + threadIdx.x;   // NE exact
    atomicAdd(&gDeg[__ldg(src + e)], 1);
}

__global__ void k_scan() {   // single block, 1024 threads
    __shared__ int sp[1024];
    const int CH = 98;                        // 1024*98 >= NN
    int t = threadIdx.x;
    int lo = t * CH;
    int hi = lo + CH; if (hi > NN) hi = NN;
    int s = 0;
    for (int i = lo; i < hi; i++) s += gDeg[i];
    sp[t] = s;
    __syncthreads();
    for (int off = 1; off < 1024; off <<= 1) {
        int v = (t >= off) ? sp[t - off] : 0;
        __syncthreads();
        sp[t] += v;
        __syncthreads();
    }
    int run = sp[t] - s;                      // exclusive prefix
    for (int i = lo; i < hi; i++) {
        gOff[i] = run; gOffCur[i] = run;
        run += gDeg[i];
    }
}

__global__ __launch_bounds__(256) void k_scatter(const int* __restrict__ src,
                                                 const int* __restrict__ dst,
                                                 const float* __restrict__ ew) {
    int e = blockIdx.x * 256 + threadIdx.x;   // NE exact
    int s = __ldg(src + e);
    int pos = atomicAdd(&gOffCur[s], 1);
    gEpack[pos] = make_int4(__ldg(dst + e), e, __float_as_int(__ldg(ew + e)), 0);
}

// ---------------- init: R = D - segsum(xE, src), warp per node ----------------
__global__ __launch_bounds__(256) void k_init_csr(const float* __restrict__ xE,
                                                  const float* __restrict__ D,
                                                  float* __restrict__ outR) {
    int wid = threadIdx.x >> 5, lane = threadIdx.x & 31;
    int n = blockIdx.x * 8 + wid;             // grid = NN/8 exact
    int start = gOff[n], deg = gDeg[n];
    const int4* ep = gEpack + start;
    float acc = 0.f;
    for (int j = 0; j < deg; j++) {
        int4 E = __ldg(ep + j);
        acc += __ldg(xE + (size_t)E.y * 32 + lane);
    }
    float r = __ldg(D + n*32 + lane) - acc;
    gR[n*32 + lane] = r;
    outR[n*32 + lane] = r;
}

// ---------------- fused Y0 + P,Q (edge order, e<NN) ----------------
__global__ __launch_bounds__(256) void k_y0pq(const float4* __restrict__ xE4,
                                              const float* __restrict__ ew,
                                              const int* __restrict__ src,
                                              const int* __restrict__ dst,
                                              const float* __restrict__ Wg,
                                              const float* __restrict__ Ws) {
    __shared__ float sWg[1024], sWs[1024];
    __shared__ float sY[32][33];
    int t = threadIdx.x;
    for (int i = t; i < 1024; i += 256) { sWg[i] = __ldg(Wg + i); sWs[i] = __ldg(Ws + i); }
    int idx = blockIdx.x * 256 + t;           // NN*8
    int e = idx >> 3, c = idx & 7, el = t >> 3, k0 = c * 4;
    int s = __ldg(src + e), d = __ldg(dst + e);
    float w = __ldg(ew + e);
    float4 x = __ldg(xE4 + idx);
    float4 rs = ((const float4*)gR)[s*8 + c];
    float4 rd = ((const float4*)gR)[d*8 + c];
    sY[el][k0+0] = x.x + w*(rs.x - rd.x);
    sY[el][k0+1] = x.y + w*(rs.y - rd.y);
    sY[el][k0+2] = x.z + w*(rs.z - rd.z);
    sY[el][k0+3] = x.w + w*(rs.w - rd.w);
    __syncthreads();
    float4 p = make_float4(0,0,0,0), q = make_float4(0,0,0,0);
    #pragma unroll
    for (int k = 0; k < 32; k++) {
        float yk = sY[el][k];
        float4 wg = *(const float4*)(sWg + k*32 + k0);
        float4 ws = *(const float4*)(sWs + k*32 + k0);
        p.x += yk*wg.x; p.y += yk*wg.y; p.z += yk*wg.z; p.w += yk*wg.w;
        q.x += yk*ws.x; q.y += yk*ws.y; q.z += yk*ws.z; q.w += yk*ws.w;
    }
    ((float4*)gP)[idx] = p;
    ((float4*)gQ)[idx] = q;
}

// ---------------- main edge pass: warp per node, no atomics ----------------
__global__ __launch_bounds__(256) void k_edge_csr(const float* __restrict__ D,
                                                  float* __restrict__ outR) {
    int wid = threadIdx.x >> 5, lane = threadIdx.x & 31;
    int n = blockIdx.x * 8 + wid;             // grid = NN/8 exact
    float ps = __ldg(gP + (size_t)n*32 + lane);
    int start = gOff[n], deg = gDeg[n];
    const int4* ep = gEpack + start;
    float ag = 0.f, as = 0.f;
    for (int j = 0; j < deg; j++) {
        int4 E = __ldg(ep + j);
        int d = E.x, eid = E.y;
        float w = __int_as_float(E.z);
        float pd = __ldg(gP + (size_t)d*32 + lane);
        float qd = __ldg(gQ + (size_t)d*32 + lane);
        float tg = tanha(w * (ps - pd));
        float ts = tanha(w * qd);
        ag += tg; as += ts;
        if (eid < NN) {
            gTG[(size_t)eid*32 + lane] = tg;
            gTS[(size_t)eid*32 + lane] = ts;
        }
    }
    // epilogue GEMM via warp shuffles; weights stay L1-resident via __ldg
    float acc = 0.f;
    #pragma unroll
    for (int k = 0; k < 32; k++) {
        float a = __shfl_sync(0xffffffffu, ag, k);
        float b = __shfl_sync(0xffffffffu, as, k);
        acc += a * __ldg(gWgT + k*32 + lane) + b * __ldg(gWsT + k*32 + lane);
    }
    float r = __ldg(D + n*32 + lane) - acc;
    gR[n*32 + lane] = r;
    outR[n*32 + lane] = r;
}

// ---------------- fused Zref + P,Q for next iter (edge order, e<NN) ----------------
__global__ __launch_bounds__(256) void k_zpq(const float* __restrict__ ew,
                                             const int* __restrict__ src,
                                             const int* __restrict__ dst,
                                             const float* __restrict__ Wg,
                                             const float* __restrict__ Ws) {
    __shared__ float sWgT[1024], sWsT[1024], sWg[1024], sWs[1024];
    __shared__ float sA[32][33], sB[32][33], sY[32][33];
    int t = threadIdx.x;
    for (int i = t; i < 1024; i += 256) {
        sWgT[i] = gWgT[i]; sWsT[i] = gWsT[i];
        sWg[i] = __ldg(Wg + i); sWs[i] = __ldg(Ws + i);
    }
    int idx = blockIdx.x * 256 + t;           // NN*8
    int e = idx >> 3, c = idx & 7, el = t >> 3, k0 = c * 4;
    float4 va = ((const float4*)gTG)[idx];
    float4 vb = ((const float4*)gTS)[idx];
    sA[el][k0+0]=va.x; sA[el][k0+1]=va.y; sA[el][k0+2]=va.z; sA[el][k0+3]=va.w;
    sB[el][k0+0]=vb.x; sB[el][k0+1]=vb.y; sB[el][k0+2]=vb.z; sB[el][k0+3]=vb.w;
    int s = __ldg(src + e), d = __ldg(dst + e);
    float w = __ldg(ew + e);
    float4 rs = ((const float4*)gR)[s*8 + c];
    float4 rd = ((const float4*)gR)[d*8 + c];
    __syncthreads();
    float4 acc;
    acc.x = w*(rs.x-rd.x); acc.y = w*(rs.y-rd.y);
    acc.z = w*(rs.z-rd.z); acc.w = w*(rs.w-rd.w);
    #pragma unroll
    for (int k = 0; k < 32; k++) {
        float ak = sA[el][k], bk = sB[el][k];
        float4 wg = *(const float4*)(sWgT + k*32 + k0);
        float4 ws = *(const float4*)(sWsT + k*32 + k0);
        acc.x += ak*wg.x + bk*ws.x;
        acc.y += ak*wg.y + bk*ws.y;
        acc.z += ak*wg.z + bk*ws.z;
        acc.w += ak*wg.w + bk*ws.w;
    }
    __syncthreads();
    sY[el][k0+0]=acc.x; sY[el][k0+1]=acc.y; sY[el][k0+2]=acc.z; sY[el][k0+3]=acc.w;
    __syncthreads();
    float4 p = make_float4(0,0,0,0), q = make_float4(0,0,0,0);
    #pragma unroll
    for (int k = 0; k < 32; k++) {
        float yk = sY[el][k];
        float4 wg = *(const float4*)(sWg + k*32 + k0);
        float4 ws = *(const float4*)(sWs + k*32 + k0);
        p.x += yk*wg.x; p.y += yk*wg.y; p.z += yk*wg.z; p.w += yk*wg.w;
        q.x += yk*ws.x; q.y += yk*ws.y; q.z += yk*ws.z; q.w += yk*ws.w;
    }
    ((float4*)gP)[idx] = p;
    ((float4*)gQ)[idx] = q;
}

// ---------------- RW = R @ We ----------------
__global__ __launch_bounds__(256) void k_rw(const float* __restrict__ We) {
    __shared__ float sW[1024];
    __shared__ float sR[32][33];
    int t = threadIdx.x;
    for (int i = t; i < 1024; i += 256) sW[i] = __ldg(We + i);
    int idx = blockIdx.x * 256 + t;           // NN*8
    int el = t >> 3, k0 = (idx & 7) * 4;
    float4 v = ((const float4*)gR)[idx];
    sR[el][k0+0]=v.x; sR[el][k0+1]=v.y; sR[el][k0+2]=v.z; sR[el][k0+3]=v.w;
    __syncthreads();
    float4 acc = make_float4(0,0,0,0);
    #pragma unroll
    for (int k = 0; k < 32; k++) {
        float rk = sR[el][k];
        float4 w4 = *(const float4*)(sW + k*32 + k0);
        acc.x += rk*w4.x; acc.y += rk*w4.y;
        acc.z += rk*w4.z; acc.w += rk*w4.w;
    }
    ((float4*)gRW)[idx] = acc;
}

// ---------------- final outputs (edge order) ----------------
__global__ __launch_bounds__(256) void k_out(const float* __restrict__ ew,
                                             const int* __restrict__ src,
                                             const int* __restrict__ dst,
                                             float4* __restrict__ outX,
                                             float4* __restrict__ outXref) {
    __shared__ float sMg[1024], sMs[1024];
    __shared__ float stg[32][33], sts[32][33];
    int t = threadIdx.x;
    for (int i = t; i < 1024; i += 256) { sMg[i] = gMg[i]; sMs[i] = gMs[i]; }
    int idx = blockIdx.x * 256 + t;           // NE*8
    int e = idx >> 3, c = idx & 7, el = t >> 3, k0 = c * 4;
    int s = __ldg(src + e), d = __ldg(dst + e);
    float w = __ldg(ew + e);
    const float4* P4 = (const float4*)gP;
    const float4* Q4 = (const float4*)gQ;
    float4 ps = __ldg(P4 + s*8 + c);
    float4 pd = __ldg(P4 + d*8 + c);
    float4 qd = __ldg(Q4 + d*8 + c);
    stg[el][k0+0] = tanha(w*(ps.x-pd.x));
    stg[el][k0+1] = tanha(w*(ps.y-pd.y));
    stg[el][k0+2] = tanha(w*(ps.z-pd.z));
    stg[el][k0+3] = tanha(w*(ps.w-pd.w));
    sts[el][k0+0] = tanha(w*qd.x);
    sts[el][k0+1] = tanha(w*qd.y);
    sts[el][k0+2] = tanha(w*qd.z);
    sts[el][k0+3] = tanha(w*qd.w);
    __syncthreads();
    float4 xr = make_float4(0,0,0,0);
    #pragma unroll
    for (int k = 0; k < 32; k++) {
        float tgk = stg[el][k], tsk = sts[el][k];
        float4 mg = *(const float4*)(sMg + k*32 + k0);
        float4 ms = *(const float4*)(sMs + k*32 + k0);
        xr.x += tgk*mg.x + tsk*ms.x;
        xr.y += tgk*mg.y + tsk*ms.y;
        xr.z += tgk*mg.z + tsk*ms.z;
        xr.w += tgk*mg.w + tsk*ms.w;
    }
    const float4* RW4 = (const float4*)gRW;
    float4 rs = __ldg(RW4 + s*8 + c);
    float4 rd = __ldg(RW4 + d*8 + c);
    float4 x;
    x.x = xr.x + w*(rs.x-rd.x);
    x.y = xr.y + w*(rs.y-rd.y);
    x.z = xr.z + w*(rs.z-rd.z);
    x.w = xr.w + w*(rs.w-rd.w);
    outX[idx] = x;
    outXref[idx] = xr;
}

// ---------------- launch ----------------
extern "C" void kernel_launch(void* const* d_in, const int* in_sizes, int n_in,
                              void* d_out, int out_size) {
    const float* D  = (const float*)d_in[0];
    const float* xE = (const float*)d_in[1];
    const float* ew = (const float*)d_in[2];
    const float* Wg = (const float*)d_in[3];
    const float* Ws = (const float*)d_in[4];
    const float* We = (const float*)d_in[5];
    const int* eidx = (const int*)d_in[6];
    const int* src = eidx;
    const int* dst = eidx + NE;
    float* out = (float*)d_out;
    float4* outX    = (float4*)out;
    float4* outXref = (float4*)(out + (size_t)NE * 32);
    float*  outR    = out + (size_t)2 * NE * 32;

    const int BN = 256;
    const int gN8 = NN * 8 / BN;    // 3125
    const int gE8 = NE * 8 / BN;    // 50000
    const int gE  = NE / BN;        // 6250
    const int gNW = NN / 8;         // 12500 (warp per node)
    const int gNZ = (NN + BN - 1) / BN;

    k_prep<<<1, 1024>>>(Wg, Ws, We);
    k_zero_deg<<<gNZ, BN>>>();
    k_hist<<<gE, BN>>>(src);
    k_scan<<<1, 1024>>>();
    k_scatter<<<gE, BN>>>(src, dst, ew);
    k_init_csr<<<gNW, BN>>>(xE, D, outR);
    k_y0pq<<<gN8, BN>>>((const float4*)xE, ew, src, dst, Wg, Ws);
    for (int it = 0; it < 3; ++it) {
        k_edge_csr<<<gNW, BN>>>(D, outR);
        if (it < 2) k_zpq<<<gN8, BN>>>(ew, src, dst, Wg, Ws);
    }
    k_rw<<<gN8, BN>>>(We);
    k_out<<<gE8, BN>>>(ew, src, dst, outX, outXref);
}

// round 4
// speedup vs baseline: 1.1223x; 1.1223x over previous
#include <cuda_runtime.h>

#define NN 100000
#define NE 1600000
#define NBLK 391   // ceil(NN/256)

// ---------------- device scratch ----------------
__device__ float gP [NN*32];
__device__ float gQ [NN*32];
__device__ float gR [NN*32];
__device__ float gRW[NN*32];
__device__ float gTG[NN*32];
__device__ float gTS[NN*32];
__device__ float gWgT[1024];
__device__ float gWsT[1024];
__device__ float gMg[1024];
__device__ float gMs[1024];
__device__ int   gDeg[NN];
__device__ int   gOff[NN];
__device__ int   gOffCur[NN];
__device__ int   gPart[NBLK];
__device__ int   gPartOff[NBLK];
__device__ int4  gEpack[NE];   // {dst, eid, ew_bits, 0}

__device__ __forceinline__ float tanha(float x) {
    float y;
    asm("tanh.approx.f32 %0, %1;" : "=f"(y) : "f"(x));
    return y;
}

// ---------------- prep ----------------
__global__ void k_prep(const float* __restrict__ Wg, const float* __restrict__ Ws,
                       const float* __restrict__ We) {
    int t = threadIdx.x;
    int i = t >> 5, j = t & 31;
    gWgT[t] = Wg[j*32 + i];
    gWsT[t] = Ws[j*32 + i];
    float mg = 0.f, ms = 0.f;
    #pragma unroll
    for (int k = 0; k < 32; k++) {
        float we = We[k*32 + j];
        mg += Wg[k*32 + i] * we;
        ms += Ws[k*32 + i] * we;
    }
    gMg[t] = mg; gMs[t] = ms;
}

// ---------------- CSR build ----------------
__global__ __launch_bounds__(256) void k_zero_deg() {
    int i = blockIdx.x * 256 + threadIdx.x;
    if (i < NN) gDeg[i] = 0;
}

__global__ __launch_bounds__(256) void k_hist(const int* __restrict__ src) {
    int e = blockIdx.x * 256 + threadIdx.x;   // NE exact
    atomicAdd(&gDeg[__ldg(src + e)], 1);
}

// hierarchical scan: partial sums
__global__ __launch_bounds__(256) void k_part() {
    __shared__ int sp[256];
    int t = threadIdx.x;
    int i = blockIdx.x * 256 + t;
    int v = (i < NN) ? gDeg[i] : 0;
    sp[t] = v;
    __syncthreads();
    #pragma unroll
    for (int off = 128; off > 0; off >>= 1) {
        if (t < off) sp[t] += sp[t + off];
        __syncthreads();
    }
    if (t == 0) gPart[blockIdx.x] = sp[0];
}

// top-level scan of 391 partials (1 block, 512 threads)
__global__ void k_top() {
    __shared__ int sp[512];
    int t = threadIdx.x;
    int v = (t < NBLK) ? gPart[t] : 0;
    sp[t] = v;
    __syncthreads();
    #pragma unroll
    for (int off = 1; off < 512; off <<= 1) {
        int u = (t >= off) ? sp[t - off] : 0;
        __syncthreads();
        sp[t] += u;
        __syncthreads();
    }
    if (t < NBLK) gPartOff[t] = sp[t] - v;   // exclusive
}

// apply: per-block exclusive scan + base
__global__ __launch_bounds__(256) void k_apply() {
    __shared__ int sp[256];
    int t = threadIdx.x;
    int i = blockIdx.x * 256 + t;
    int v = (i < NN) ? gDeg[i] : 0;
    sp[t] = v;
    __syncthreads();
    #pragma unroll
    for (int off = 1; off < 256; off <<= 1) {
        int u = (t >= off) ? sp[t - off] : 0;
        __syncthreads();
        sp[t] += u;
        __syncthreads();
    }
    if (i < NN) {
        int excl = gPartOff[blockIdx.x] + sp[t] - v;
        gOff[i] = excl;
        gOffCur[i] = excl;
    }
}

__global__ __launch_bounds__(256) void k_scatter(const int* __restrict__ src,
                                                 const int* __restrict__ dst,
                                                 const float* __restrict__ ew) {
    int e = blockIdx.x * 256 + threadIdx.x;   // NE exact
    int s = __ldg(src + e);
    int pos = atomicAdd(&gOffCur[s], 1);
    gEpack[pos] = make_int4(__ldg(dst + e), e, __float_as_int(__ldg(ew + e)), 0);
}

// ---------------- init: R = D - segsum(xE, src), warp per node, unroll 4 ----------------
__global__ __launch_bounds__(256) void k_init_csr(const float* __restrict__ xE,
                                                  const float* __restrict__ D,
                                                  float* __restrict__ outR) {
    int wid = threadIdx.x >> 5, lane = threadIdx.x & 31;
    int n = blockIdx.x * 8 + wid;             // grid = NN/8 exact
    int start = gOff[n], deg = gDeg[n];
    const int4* ep = gEpack + start;
    float acc = 0.f;
    int j = 0;
    for (; j + 4 <= deg; j += 4) {
        int4 E0 = __ldg(ep + j);
        int4 E1 = __ldg(ep + j + 1);
        int4 E2 = __ldg(ep + j + 2);
        int4 E3 = __ldg(ep + j + 3);
        float v0 = __ldg(xE + (size_t)E0.y * 32 + lane);
        float v1 = __ldg(xE + (size_t)E1.y * 32 + lane);
        float v2 = __ldg(xE + (size_t)E2.y * 32 + lane);
        float v3 = __ldg(xE + (size_t)E3.y * 32 + lane);
        acc += (v0 + v1) + (v2 + v3);
    }
    for (; j < deg; j++) {
        int4 E = __ldg(ep + j);
        acc += __ldg(xE + (size_t)E.y * 32 + lane);
    }
    float r = __ldg(D + n*32 + lane) - acc;
    gR[n*32 + lane] = r;
    outR[n*32 + lane] = r;
}

// ---------------- fused Y0 + P,Q (edge order, e<NN) ----------------
__global__ __launch_bounds__(256) void k_y0pq(const float4* __restrict__ xE4,
                                              const float* __restrict__ ew,
                                              const int* __restrict__ src,
                                              const int* __restrict__ dst,
                                              const float* __restrict__ Wg,
                                              const float* __restrict__ Ws) {
    __shared__ float sWg[1024], sWs[1024];
    __shared__ float sY[32][33];
    int t = threadIdx.x;
    for (int i = t; i < 1024; i += 256) { sWg[i] = __ldg(Wg + i); sWs[i] = __ldg(Ws + i); }
    int idx = blockIdx.x * 256 + t;           // NN*8
    int e = idx >> 3, c = idx & 7, el = t >> 3, k0 = c * 4;
    int s = __ldg(src + e), d = __ldg(dst + e);
    float w = __ldg(ew + e);
    float4 x = __ldg(xE4 + idx);
    float4 rs = ((const float4*)gR)[s*8 + c];
    float4 rd = ((const float4*)gR)[d*8 + c];
    sY[el][k0+0] = x.x + w*(rs.x - rd.x);
    sY[el][k0+1] = x.y + w*(rs.y - rd.y);
    sY[el][k0+2] = x.z + w*(rs.z - rd.z);
    sY[el][k0+3] = x.w + w*(rs.w - rd.w);
    __syncthreads();
    float4 p = make_float4(0,0,0,0), q = make_float4(0,0,0,0);
    #pragma unroll
    for (int k = 0; k < 32; k++) {
        float yk = sY[el][k];
        float4 wg = *(const float4*)(sWg + k*32 + k0);
        float4 ws = *(const float4*)(sWs + k*32 + k0);
        p.x += yk*wg.x; p.y += yk*wg.y; p.z += yk*wg.z; p.w += yk*wg.w;
        q.x += yk*ws.x; q.y += yk*ws.y; q.z += yk*ws.z; q.w += yk*ws.w;
    }
    ((float4*)gP)[idx] = p;
    ((float4*)gQ)[idx] = q;
}

// ---------------- main edge pass: warp per node, no atomics, unroll 4 ----------------
__global__ __launch_bounds__(256) void k_edge_csr(const float* __restrict__ D,
                                                  float* __restrict__ outR) {
    int wid = threadIdx.x >> 5, lane = threadIdx.x & 31;
    int n = blockIdx.x * 8 + wid;             // grid = NN/8 exact
    float ps = __ldg(gP + (size_t)n*32 + lane);
    int start = gOff[n], deg = gDeg[n];
    const int4* ep = gEpack + start;
    float ag = 0.f, as = 0.f;
    int j = 0;
    for (; j + 4 <= deg; j += 4) {
        int4 E0 = __ldg(ep + j);
        int4 E1 = __ldg(ep + j + 1);
        int4 E2 = __ldg(ep + j + 2);
        int4 E3 = __ldg(ep + j + 3);
        float pd0 = __ldg(gP + (size_t)E0.x * 32 + lane);
        float qd0 = __ldg(gQ + (size_t)E0.x * 32 + lane);
        float pd1 = __ldg(gP + (size_t)E1.x * 32 + lane);
        float qd1 = __ldg(gQ + (size_t)E1.x * 32 + lane);
        float pd2 = __ldg(gP + (size_t)E2.x * 32 + lane);
        float qd2 = __ldg(gQ + (size_t)E2.x * 32 + lane);
        float pd3 = __ldg(gP + (size_t)E3.x * 32 + lane);
        float qd3 = __ldg(gQ + (size_t)E3.x * 32 + lane);
        float w0 = __int_as_float(E0.z), w1 = __int_as_float(E1.z);
        float w2 = __int_as_float(E2.z), w3 = __int_as_float(E3.z);
        float tg0 = tanha(w0*(ps-pd0)), ts0 = tanha(w0*qd0);
        float tg1 = tanha(w1*(ps-pd1)), ts1 = tanha(w1*qd1);
        float tg2 = tanha(w2*(ps-pd2)), ts2 = tanha(w2*qd2);
        float tg3 = tanha(w3*(ps-pd3)), ts3 = tanha(w3*qd3);
        ag += (tg0 + tg1) + (tg2 + tg3);
        as += (ts0 + ts1) + (ts2 + ts3);
        if (E0.y < NN) { gTG[(size_t)E0.y*32 + lane] = tg0; gTS[(size_t)E0.y*32 + lane] = ts0; }
        if (E1.y < NN) { gTG[(size_t)E1.y*32 + lane] = tg1; gTS[(size_t)E1.y*32 + lane] = ts1; }
        if (E2.y < NN) { gTG[(size_t)E2.y*32 + lane] = tg2; gTS[(size_t)E2.y*32 + lane] = ts2; }
        if (E3.y < NN) { gTG[(size_t)E3.y*32 + lane] = tg3; gTS[(size_t)E3.y*32 + lane] = ts3; }
    }
    for (; j < deg; j++) {
        int4 E = __ldg(ep + j);
        float w = __int_as_float(E.z);
        float pd = __ldg(gP + (size_t)E.x * 32 + lane);
        float qd = __ldg(gQ + (size_t)E.x * 32 + lane);
        float tg = tanha(w * (ps - pd));
        float ts = tanha(w * qd);
        ag += tg; as += ts;
        if (E.y < NN) {
            gTG[(size_t)E.y*32 + lane] = tg;
            gTS[(size_t)E.y*32 + lane] = ts;
        }
    }
    // epilogue GEMM via warp shuffles; weights L1-resident via __ldg
    float acc = 0.f;
    #pragma unroll
    for (int k = 0; k < 32; k++) {
        float a = __shfl_sync(0xffffffffu, ag, k);
        float b = __shfl_sync(0xffffffffu, as, k);
        acc += a * __ldg(gWgT + k*32 + lane) + b * __ldg(gWsT + k*32 + lane);
    }
    float r = __ldg(D + n*32 + lane) - acc;
    gR[n*32 + lane] = r;
    outR[n*32 + lane] = r;
}

// ---------------- fused Zref + P,Q for next iter (edge order, e<NN) ----------------
__global__ __launch_bounds__(256) void k_zpq(const float* __restrict__ ew,
                                             const int* __restrict__ src,
                                             const int* __restrict__ dst,
                                             const float* __restrict__ Wg,
                                             const float* __restrict__ Ws) {
    __shared__ float sWgT[1024], sWsT[1024], sWg[1024], sWs[1024];
    __shared__ float sA[32][33], sB[32][33], sY[32][33];
    int t = threadIdx.x;
    for (int i = t; i < 1024; i += 256) {
        sWgT[i] = gWgT[i]; sWsT[i] = gWsT[i];
        sWg[i] = __ldg(Wg + i); sWs[i] = __ldg(Ws + i);
    }
    int idx = blockIdx.x * 256 + t;           // NN*8
    int e = idx >> 3, c = idx & 7, el = t >> 3, k0 = c * 4;
    float4 va = ((const float4*)gTG)[idx];
    float4 vb = ((const float4*)gTS)[idx];
    sA[el][k0+0]=va.x; sA[el][k0+1]=va.y; sA[el][k0+2]=va.z; sA[el][k0+3]=va.w;
    sB[el][k0+0]=vb.x; sB[el][k0+1]=vb.y; sB[el][k0+2]=vb.z; sB[el][k0+3]=vb.w;
    int s = __ldg(src + e), d = __ldg(dst + e);
    float w = __ldg(ew + e);
    float4 rs = ((const float4*)gR)[s*8 + c];
    float4 rd = ((const float4*)gR)[d*8 + c];
    __syncthreads();
    float4 acc;
    acc.x = w*(rs.x-rd.x); acc.y = w*(rs.y-rd.y);
    acc.z = w*(rs.z-rd.z); acc.w = w*(rs.w-rd.w);
    #pragma unroll
    for (int k = 0; k < 32; k++) {
        float ak = sA[el][k], bk = sB[el][k];
        float4 wg = *(const float4*)(sWgT + k*32 + k0);
        float4 ws = *(const float4*)(sWsT + k*32 + k0);
        acc.x += ak*wg.x + bk*ws.x;
        acc.y += ak*wg.y + bk*ws.y;
        acc.z += ak*wg.z + bk*ws.z;
        acc.w += ak*wg.w + bk*ws.w;
    }
    __syncthreads();
    sY[el][k0+0]=acc.x; sY[el][k0+1]=acc.y; sY[el][k0+2]=acc.z; sY[el][k0+3]=acc.w;
    __syncthreads();
    float4 p = make_float4(0,0,0,0), q = make_float4(0,0,0,0);
    #pragma unroll
    for (int k = 0; k < 32; k++) {
        float yk = sY[el][k];
        float4 wg = *(const float4*)(sWg + k*32 + k0);
        float4 ws = *(const float4*)(sWs + k*32 + k0);
        p.x += yk*wg.x; p.y += yk*wg.y; p.z += yk*wg.z; p.w += yk*wg.w;
        q.x += yk*ws.x; q.y += yk*ws.y; q.z += yk*ws.z; q.w += yk*ws.w;
    }
    ((float4*)gP)[idx] = p;
    ((float4*)gQ)[idx] = q;
}

// ---------------- RW = R @ We ----------------
__global__ __launch_bounds__(256) void k_rw(const float* __restrict__ We) {
    __shared__ float sW[1024];
    __shared__ float sR[32][33];
    int t = threadIdx.x;
    for (int i = t; i < 1024; i += 256) sW[i] = __ldg(We + i);
    int idx = blockIdx.x * 256 + t;           // NN*8
    int el = t >> 3, k0 = (idx & 7) * 4;
    float4 v = ((const float4*)gR)[idx];
    sR[el][k0+0]=v.x; sR[el][k0+1]=v.y; sR[el][k0+2]=v.z; sR[el][k0+3]=v.w;
    __syncthreads();
    float4 acc = make_float4(0,0,0,0);
    #pragma unroll
    for (int k = 0; k < 32; k++) {
        float rk = sR[el][k];
        float4 w4 = *(const float4*)(sW + k*32 + k0);
        acc.x += rk*w4.x; acc.y += rk*w4.y;
        acc.z += rk*w4.z; acc.w += rk*w4.w;
    }
    ((float4*)gRW)[idx] = acc;
}

// ---------------- final outputs (edge order) ----------------
__global__ __launch_bounds__(256) void k_out(const float* __restrict__ ew,
                                             const int* __restrict__ src,
                                             const int* __restrict__ dst,
                                             float4* __restrict__ outX,
                                             float4* __restrict__ outXref) {
    __shared__ float sMg[1024], sMs[1024];
    __shared__ float stg[32][33], sts[32][33];
    int t = threadIdx.x;
    for (int i = t; i < 1024; i += 256) { sMg[i] = gMg[i]; sMs[i] = gMs[i]; }
    int idx = blockIdx.x * 256 + t;           // NE*8
    int e = idx >> 3, c = idx & 7, el = t >> 3, k0 = c * 4;
    int s = __ldg(src + e), d = __ldg(dst + e);
    float w = __ldg(ew + e);
    const float4* P4 = (const float4*)gP;
    const float4* Q4 = (const float4*)gQ;
    float4 ps = __ldg(P4 + s*8 + c);
    float4 pd = __ldg(P4 + d*8 + c);
    float4 qd = __ldg(Q4 + d*8 + c);
    stg[el][k0+0] = tanha(w*(ps.x-pd.x));
    stg[el][k0+1] = tanha(w*(ps.y-pd.y));
    stg[el][k0+2] = tanha(w*(ps.z-pd.z));
    stg[el][k0+3] = tanha(w*(ps.w-pd.w));
    sts[el][k0+0] = tanha(w*qd.x);
    sts[el][k0+1] = tanha(w*qd.y);
    sts[el][k0+2] = tanha(w*qd.z);
    sts[el][k0+3] = tanha(w*qd.w);
    __syncthreads();
    float4 xr = make_float4(0,0,0,0);
    #pragma unroll
    for (int k = 0; k < 32; k++) {
        float tgk = stg[el][k], tsk = sts[el][k];
        float4 mg = *(const float4*)(sMg + k*32 + k0);
        float4 ms = *(const float4*)(sMs + k*32 + k0);
        xr.x += tgk*mg.x + tsk*ms.x;
        xr.y += tgk*mg.y + tsk*ms.y;
        xr.z += tgk*mg.z + tsk*ms.z;
        xr.w += tgk*mg.w + tsk*ms.w;
    }
    const float4* RW4 = (const float4*)gRW;
    float4 rs = __ldg(RW4 + s*8 + c);
    float4 rd = __ldg(RW4 + d*8 + c);
    float4 x;
    x.x = xr.x + w*(rs.x-rd.x);
    x.y = xr.y + w*(rs.y-rd.y);
    x.z = xr.z + w*(rs.z-rd.z);
    x.w = xr.w + w*(rs.w-rd.w);
    outX[idx] = x;
    outXref[idx] = xr;
}

// ---------------- launch ----------------
extern "C" void kernel_launch(void* const* d_in, const int* in_sizes, int n_in,
                              void* d_out, int out_size) {
    const float* D  = (const float*)d_in[0];
    const float* xE = (const float*)d_in[1];
    const float* ew = (const float*)d_in[2];
    const float* Wg = (const float*)d_in[3];
    const float* Ws = (const float*)d_in[4];
    const float* We = (const float*)d_in[5];
    const int* eidx = (const int*)d_in[6];
    const int* src = eidx;
    const int* dst = eidx + NE;
    float* out = (float*)d_out;
    float4* outX    = (float4*)out;
    float4* outXref = (float4*)(out + (size_t)NE * 32);
    float*  outR    = out + (size_t)2 * NE * 32;

    const int BN = 256;
    const int gN8 = NN * 8 / BN;    // 3125
    const int gE8 = NE * 8 / BN;    // 50000
    const int gE  = NE / BN;        // 6250
    const int gNW = NN / 8;         // 12500 (warp per node)

    k_prep<<<1, 1024>>>(Wg, Ws, We);
    k_zero_deg<<<NBLK, BN>>>();
    k_hist<<<gE, BN>>>(src);
    k_part<<<NBLK, BN>>>();
    k_top<<<1, 512>>>();
    k_apply<<<NBLK, BN>>>();
    k_scatter<<<gE, BN>>>(src, dst, ew);
    k_init_csr<<<gNW, BN>>>(xE, D, outR);
    k_y0pq<<<gN8, BN>>>((const float4*)xE, ew, src, dst, Wg, Ws);
    for (int it = 0; it < 3; ++it) {
        k_edge_csr<<<gNW, BN>>>(D, outR);
        if (it < 2) k_zpq<<<gN8, BN>>>(ew, src, dst, Wg, Ws);
    }
    k_rw<<<gN8, BN>>>(We);
    k_out<<<gE8, BN>>>(ew, src, dst, outX, outXref);
}

// round 6
// speedup vs baseline: 1.2135x; 1.0813x over previous
#include <cuda_runtime.h>

#define NN 100000
#define NE 1600000
#define NBLK 391   // ceil(NN/256)

// ---------------- device scratch ----------------
__device__ float gPa [NN*32];   // P rows buffer A
__device__ float gPQa[NN*64];   // interleaved {P,Q} buffer A
__device__ float gPb [NN*32];   // P rows buffer B
__device__ float gPQb[NN*64];   // interleaved {P,Q} buffer B
__device__ float gR [NN*32];
__device__ float gRW[NN*32];
__device__ float gWgT[1024];
__device__ float gWsT[1024];
__device__ float gMg[1024];
__device__ float gMs[1024];
__device__ int   gDeg[NN];      // zero at entry (static init / re-zeroed each call)
__device__ int   gOff[NN];
__device__ int   gOffCur[NN];
__device__ int   gPart[NBLK];
__device__ int   gPartOff[NBLK];
__device__ int2  gEdge[NE];     // {dst, ew_bits}
__device__ int   gEid[NE];      // original edge id (init pass only)

__device__ __forceinline__ float tanha(float x) {
    float y;
    asm("tanh.approx.f32 %0, %1;" : "=f"(y) : "f"(x));
    return y;
}

// ---------------- prep ----------------
__global__ void k_prep(const float* __restrict__ Wg, const float* __restrict__ Ws,
                       const float* __restrict__ We) {
    int t = threadIdx.x;
    int i = t >> 5, j = t & 31;
    gWgT[t] = Wg[j*32 + i];
    gWsT[t] = Ws[j*32 + i];
    float mg = 0.f, ms = 0.f;
    #pragma unroll
    for (int k = 0; k < 32; k++) {
        float we = We[k*32 + j];
        mg += Wg[k*32 + i] * we;
        ms += Ws[k*32 + i] * we;
    }
    gMg[t] = mg; gMs[t] = ms;
}

// ---------------- CSR build ----------------
__global__ __launch_bounds__(256) void k_hist(const int* __restrict__ src) {
    int e = blockIdx.x * 256 + threadIdx.x;   // NE exact
    atomicAdd(&gDeg[__ldg(src + e)], 1);
}

__global__ __launch_bounds__(256) void k_part() {
    __shared__ int sp[256];
    int t = threadIdx.x;
    int i = blockIdx.x * 256 + t;
    int v = (i < NN) ? gDeg[i] : 0;
    sp[t] = v;
    __syncthreads();
    #pragma unroll
    for (int off = 128; off > 0; off >>= 1) {
        if (t < off) sp[t] += sp[t + off];
        __syncthreads();
    }
    if (t == 0) gPart[blockIdx.x] = sp[0];
}

__global__ void k_top() {
    __shared__ int sp[512];
    int t = threadIdx.x;
    int v = (t < NBLK) ? gPart[t] : 0;
    sp[t] = v;
    __syncthreads();
    #pragma unroll
    for (int off = 1; off < 512; off <<= 1) {
        int u = (t >= off) ? sp[t - off] : 0;
        __syncthreads();
        sp[t] += u;
        __syncthreads();
    }
    if (t < NBLK) gPartOff[t] = sp[t] - v;   // exclusive
}

__global__ __launch_bounds__(256) void k_apply() {
    __shared__ int sp[256];
    int t = threadIdx.x;
    int i = blockIdx.x * 256 + t;
    int v = (i < NN) ? gDeg[i] : 0;
    sp[t] = v;
    __syncthreads();
    #pragma unroll
    for (int off = 1; off < 256; off <<= 1) {
        int u = (t >= off) ? sp[t - off] : 0;
        __syncthreads();
        sp[t] += u;
        __syncthreads();
    }
    if (i < NN) {
        int excl = gPartOff[blockIdx.x] + sp[t] - v;
        gOff[i] = excl;
        gOffCur[i] = excl;
    }
}

__global__ __launch_bounds__(256) void k_scatter(const int* __restrict__ src,
                                                 const int* __restrict__ dst,
                                                 const float* __restrict__ ew) {
    int e = blockIdx.x * 256 + threadIdx.x;   // NE exact
    int s = __ldg(src + e);
    int pos = atomicAdd(&gOffCur[s], 1);
    gEdge[pos] = make_int2(__ldg(dst + e), __float_as_int(__ldg(ew + e)));
    gEid[pos] = e;
}

// ---------------- init: R = D - segsum(xE, src), warp per node ----------------
__global__ __launch_bounds__(256) void k_init_csr(const float* __restrict__ xE,
                                                  const float* __restrict__ D,
                                                  float* __restrict__ outR) {
    int wid = threadIdx.x >> 5, lane = threadIdx.x & 31;
    int n = blockIdx.x * 8 + wid;             // grid = NN/8 exact
    int start = gOff[n], deg = gDeg[n];
    const int* ei = gEid + start;
    float acc = 0.f;
    int j = 0;
    for (; j + 4 <= deg; j += 4) {
        int e0 = __ldg(ei + j),     e1 = __ldg(ei + j + 1);
        int e2 = __ldg(ei + j + 2), e3 = __ldg(ei + j + 3);
        float v0 = __ldg(xE + (size_t)e0 * 32 + lane);
        float v1 = __ldg(xE + (size_t)e1 * 32 + lane);
        float v2 = __ldg(xE + (size_t)e2 * 32 + lane);
        float v3 = __ldg(xE + (size_t)e3 * 32 + lane);
        acc += (v0 + v1) + (v2 + v3);
    }
    for (; j < deg; j++) {
        int e = __ldg(ei + j);
        acc += __ldg(xE + (size_t)e * 32 + lane);
    }
    float r = __ldg(D + n*32 + lane) - acc;
    gR[n*32 + lane] = r;
    outR[n*32 + lane] = r;
}

// ---------------- fused Y0 + P,Q (edge order, e<NN) -> buffer A ----------------
__global__ __launch_bounds__(256) void k_y0pq(const float4* __restrict__ xE4,
                                              const float* __restrict__ ew,
                                              const int* __restrict__ src,
                                              const int* __restrict__ dst,
                                              const float* __restrict__ Wg,
                                              const float* __restrict__ Ws,
                                              float4* __restrict__ Pout,
                                              float4* __restrict__ PQout) {
    __shared__ float sWg[1024], sWs[1024];
    __shared__ float sY[32][33];
    int t = threadIdx.x;
    for (int i = t; i < 1024; i += 256) { sWg[i] = __ldg(Wg + i); sWs[i] = __ldg(Ws + i); }
    int idx = blockIdx.x * 256 + t;           // NN*8
    int e = idx >> 3, c = idx & 7, el = t >> 3, k0 = c * 4;
    int s = __ldg(src + e), d = __ldg(dst + e);
    float w = __ldg(ew + e);
    float4 x = __ldg(xE4 + idx);
    float4 rs = ((const float4*)gR)[s*8 + c];
    float4 rd = ((const float4*)gR)[d*8 + c];
    sY[el][k0+0] = x.x + w*(rs.x - rd.x);
    sY[el][k0+1] = x.y + w*(rs.y - rd.y);
    sY[el][k0+2] = x.z + w*(rs.z - rd.z);
    sY[el][k0+3] = x.w + w*(rs.w - rd.w);
    __syncthreads();
    float4 p = make_float4(0,0,0,0), q = make_float4(0,0,0,0);
    #pragma unroll
    for (int k = 0; k < 32; k++) {
        float yk = sY[el][k];
        float4 wg = *(const float4*)(sWg + k*32 + k0);
        float4 ws = *(const float4*)(sWs + k*32 + k0);
        p.x += yk*wg.x; p.y += yk*wg.y; p.z += yk*wg.z; p.w += yk*wg.w;
        q.x += yk*ws.x; q.y += yk*ws.y; q.z += yk*ws.z; q.w += yk*ws.w;
    }
    Pout[idx] = p;
    PQout[e*16 + c*2 + 0] = make_float4(p.x, q.x, p.y, q.y);
    PQout[e*16 + c*2 + 1] = make_float4(p.z, q.z, p.w, q.w);
}

// ---------------- main edge pass: warp per node, packed PQ gather ----------------
__global__ __launch_bounds__(256) void k_edge_csr(const float* __restrict__ P,
                                                  const float2* __restrict__ PQ2,
                                                  const float* __restrict__ D,
                                                  const float* __restrict__ We,
                                                  float* __restrict__ outR,
                                                  int last) {
    int wid = threadIdx.x >> 5, lane = threadIdx.x & 31;
    int n = blockIdx.x * 8 + wid;             // grid = NN/8 exact
    float ps = __ldg(P + (size_t)n*32 + lane);
    int start = gOff[n], deg = gDeg[n];
    const int2* ep = gEdge + start;
    float ag = 0.f, as = 0.f;
    int j = 0;
    for (; j + 4 <= deg; j += 4) {
        int2 E0 = __ldg(ep + j);
        int2 E1 = __ldg(ep + j + 1);
        int2 E2 = __ldg(ep + j + 2);
        int2 E3 = __ldg(ep + j + 3);
        float2 pq0 = __ldg(PQ2 + (size_t)E0.x * 32 + lane);
        float2 pq1 = __ldg(PQ2 + (size_t)E1.x * 32 + lane);
        float2 pq2 = __ldg(PQ2 + (size_t)E2.x * 32 + lane);
        float2 pq3 = __ldg(PQ2 + (size_t)E3.x * 32 + lane);
        float w0 = __int_as_float(E0.y), w1 = __int_as_float(E1.y);
        float w2 = __int_as_float(E2.y), w3 = __int_as_float(E3.y);
        float tg0 = tanha(w0*(ps-pq0.x)), ts0 = tanha(w0*pq0.y);
        float tg1 = tanha(w1*(ps-pq1.x)), ts1 = tanha(w1*pq1.y);
        float tg2 = tanha(w2*(ps-pq2.x)), ts2 = tanha(w2*pq2.y);
        float tg3 = tanha(w3*(ps-pq3.x)), ts3 = tanha(w3*pq3.y);
        ag += (tg0 + tg1) + (tg2 + tg3);
        as += (ts0 + ts1) + (ts2 + ts3);
    }
    for (; j < deg; j++) {
        int2 E = __ldg(ep + j);
        float w = __int_as_float(E.y);
        float2 pq = __ldg(PQ2 + (size_t)E.x * 32 + lane);
        ag += tanha(w*(ps-pq.x));
        as += tanha(w*pq.y);
    }
    // epilogue GEMM via warp shuffles
    float acc = 0.f;
    #pragma unroll
    for (int k = 0; k < 32; k++) {
        float a = __shfl_sync(0xffffffffu, ag, k);
        float b = __shfl_sync(0xffffffffu, as, k);
        acc += a * __ldg(gWgT + k*32 + lane) + b * __ldg(gWsT + k*32 + lane);
    }
    float r = __ldg(D + n*32 + lane) - acc;
    gR[n*32 + lane] = r;
    outR[n*32 + lane] = r;
    if (last) {
        // RW = R @ We fused here (R lives in registers)
        float rw = 0.f;
        #pragma unroll
        for (int k = 0; k < 32; k++) {
            float rk = __shfl_sync(0xffffffffu, r, k);
            rw += rk * __ldg(We + k*32 + lane);
        }
        gRW[n*32 + lane] = rw;
        if (lane == 0) gDeg[n] = 0;   // restore zero invariant for next replay
    }
}

// ---------------- fused Zref + P,Q for next iter: reads buf IN, writes buf OUT ----------------
__global__ __launch_bounds__(256) void k_zpq(const float* __restrict__ ew,
                                             const int* __restrict__ src,
                                             const int* __restrict__ dst,
                                             const float* __restrict__ Wg,
                                             const float* __restrict__ Ws,
                                             const float4* __restrict__ Pin,
                                             const float4* __restrict__ PQin,
                                             float4* __restrict__ Pout,
                                             float4* __restrict__ PQout) {
    __shared__ float sWgT[1024], sWsT[1024], sWg[1024], sWs[1024];
    __shared__ float sA[32][33], sB[32][33], sY[32][33];
    int t = threadIdx.x;
    for (int i = t; i < 1024; i += 256) {
        sWgT[i] = gWgT[i]; sWsT[i] = gWsT[i];
        sWg[i] = __ldg(Wg + i); sWs[i] = __ldg(Ws + i);
    }
    int idx = blockIdx.x * 256 + t;           // NN*8
    int e = idx >> 3, c = idx & 7, el = t >> 3, k0 = c * 4;
    int s = __ldg(src + e), d = __ldg(dst + e);
    float w = __ldg(ew + e);
    float4 ps  = __ldg(Pin + s*8 + c);
    float4 pqa = __ldg(PQin + d*16 + c*2 + 0);  // {P[k0],Q[k0],P[k0+1],Q[k0+1]}
    float4 pqb = __ldg(PQin + d*16 + c*2 + 1);
    sA[el][k0+0] = tanha(w*(ps.x - pqa.x));
    sA[el][k0+1] = tanha(w*(ps.y - pqa.z));
    sA[el][k0+2] = tanha(w*(ps.z - pqb.x));
    sA[el][k0+3] = tanha(w*(ps.w - pqb.z));
    sB[el][k0+0] = tanha(w*pqa.y);
    sB[el][k0+1] = tanha(w*pqa.w);
    sB[el][k0+2] = tanha(w*pqb.y);
    sB[el][k0+3] = tanha(w*pqb.w);
    float4 rs = ((const float4*)gR)[s*8 + c];
    float4 rd = ((const float4*)gR)[d*8 + c];
    __syncthreads();
    float4 acc;
    acc.x = w*(rs.x-rd.x); acc.y = w*(rs.y-rd.y);
    acc.z = w*(rs.z-rd.z); acc.w = w*(rs.w-rd.w);
    #pragma unroll
    for (int k = 0; k < 32; k++) {
        float ak = sA[el][k], bk = sB[el][k];
        float4 wg = *(const float4*)(sWgT + k*32 + k0);
        float4 ws = *(const float4*)(sWsT + k*32 + k0);
        acc.x += ak*wg.x + bk*ws.x;
        acc.y += ak*wg.y + bk*ws.y;
        acc.z += ak*wg.z + bk*ws.z;
        acc.w += ak*wg.w + bk*ws.w;
    }
    __syncthreads();
    sY[el][k0+0]=acc.x; sY[el][k0+1]=acc.y; sY[el][k0+2]=acc.z; sY[el][k0+3]=acc.w;
    __syncthreads();
    float4 p = make_float4(0,0,0,0), q = make_float4(0,0,0,0);
    #pragma unroll
    for (int k = 0; k < 32; k++) {
        float yk = sY[el][k];
        float4 wg = *(const float4*)(sWg + k*32 + k0);
        float4 ws = *(const float4*)(sWs + k*32 + k0);
        p.x += yk*wg.x; p.y += yk*wg.y; p.z += yk*wg.z; p.w += yk*wg.w;
        q.x += yk*ws.x; q.y += yk*ws.y; q.z += yk*ws.z; q.w += yk*ws.w;
    }
    Pout[idx] = p;
    PQout[e*16 + c*2 + 0] = make_float4(p.x, q.x, p.y, q.y);
    PQout[e*16 + c*2 + 1] = make_float4(p.z, q.z, p.w, q.w);
}

// ---------------- final outputs (edge order) ----------------
__global__ __launch_bounds__(256) void k_out(const float* __restrict__ ew,
                                             const int* __restrict__ src,
                                             const int* __restrict__ dst,
                                             const float4* __restrict__ Pin,
                                             const float4* __restrict__ PQin,
                                             float4* __restrict__ outX,
                                             float4* __restrict__ outXref) {
    __shared__ float sMg[1024], sMs[1024];
    __shared__ float stg[32][33], sts[32][33];
    int t = threadIdx.x;
    for (int i = t; i < 1024; i += 256) { sMg[i] = gMg[i]; sMs[i] = gMs[i]; }
    int idx = blockIdx.x * 256 + t;           // NE*8
    int e = idx >> 3, c = idx & 7, el = t >> 3, k0 = c * 4;
    int s = __ldg(src + e), d = __ldg(dst + e);
    float w = __ldg(ew + e);
    float4 ps  = __ldg(Pin + s*8 + c);
    float4 pqa = __ldg(PQin + d*16 + c*2 + 0);
    float4 pqb = __ldg(PQin + d*16 + c*2 + 1);
    stg[el][k0+0] = tanha(w*(ps.x - pqa.x));
    stg[el][k0+1] = tanha(w*(ps.y - pqa.z));
    stg[el][k0+2] = tanha(w*(ps.z - pqb.x));
    stg[el][k0+3] = tanha(w*(ps.w - pqb.z));
    sts[el][k0+0] = tanha(w*pqa.y);
    sts[el][k0+1] = tanha(w*pqa.w);
    sts[el][k0+2] = tanha(w*pqb.y);
    sts[el][k0+3] = tanha(w*pqb.w);
    __syncthreads();
    float4 xr = make_float4(0,0,0,0);
    #pragma unroll
    for (int k = 0; k < 32; k++) {
        float tgk = stg[el][k], tsk = sts[el][k];
        float4 mg = *(const float4*)(sMg + k*32 + k0);
        float4 ms = *(const float4*)(sMs + k*32 + k0);
        xr.x += tgk*mg.x + tsk*ms.x;
        xr.y += tgk*mg.y + tsk*ms.y;
        xr.z += tgk*mg.z + tsk*ms.z;
        xr.w += tgk*mg.w + tsk*ms.w;
    }
    const float4* RW4 = (const float4*)gRW;
    float4 rs = __ldg(RW4 + s*8 + c);
    float4 rd = __ldg(RW4 + d*8 + c);
    float4 x;
    x.x = xr.x + w*(rs.x-rd.x);
    x.y = xr.y + w*(rs.y-rd.y);
    x.z = xr.z + w*(rs.z-rd.z);
    x.w = xr.w + w*(rs.w-rd.w);
    outX[idx] = x;
    outXref[idx] = xr;
}

// ---------------- launch ----------------
extern "C" void kernel_launch(void* const* d_in, const int* in_sizes, int n_in,
                              void* d_out, int out_size) {
    const float* D  = (const float*)d_in[0];
    const float* xE = (const float*)d_in[1];
    const float* ew = (const float*)d_in[2];
    const float* Wg = (const float*)d_in[3];
    const float* Ws = (const float*)d_in[4];
    const float* We = (const float*)d_in[5];
    const int* eidx = (const int*)d_in[6];
    const int* src = eidx;
    const int* dst = eidx + NE;
    float* out = (float*)d_out;
    float4* outX    = (float4*)out;
    float4* outXref = (float4*)(out + (size_t)NE * 32);
    float*  outR    = out + (size_t)2 * NE * 32;

    // resolve ping-pong buffer addresses (host-side query; capture-safe, no alloc)
    static float *Pa = nullptr, *PQa = nullptr, *Pb = nullptr, *PQb = nullptr;
    if (!Pa) {
        cudaGetSymbolAddress((void**)&Pa,  gPa);
        cudaGetSymbolAddress((void**)&PQa, gPQa);
        cudaGetSymbolAddress((void**)&Pb,  gPb);
        cudaGetSymbolAddress((void**)&PQb, gPQb);
    }

    const int BN = 256;
    const int gN8 = NN * 8 / BN;    // 3125
    const int gE8 = NE * 8 / BN;    // 50000
    const int gE  = NE / BN;        // 6250
    const int gNW = NN / 8;         // 12500 (warp per node)

    k_prep<<<1, 1024>>>(Wg, Ws, We);
    k_hist<<<gE, BN>>>(src);
    k_part<<<NBLK, BN>>>();
    k_top<<<1, 512>>>();
    k_apply<<<NBLK, BN>>>();
    k_scatter<<<gE, BN>>>(src, dst, ew);
    k_init_csr<<<gNW, BN>>>(xE, D, outR);
    k_y0pq<<<gN8, BN>>>((const float4*)xE, ew, src, dst, Wg, Ws,
                        (float4*)Pa, (float4*)PQa);
    // it0: read A; zpq A->B
    k_edge_csr<<<gNW, BN>>>(Pa, (const float2*)PQa, D, We, outR, 0);
    k_zpq<<<gN8, BN>>>(ew, src, dst, Wg, Ws,
                       (const float4*)Pa, (const float4*)PQa,
                       (float4*)Pb, (float4*)PQb);
    // it1: read B; zpq B->A
    k_edge_csr<<<gNW, BN>>>(Pb, (const float2*)PQb, D, We, outR, 0);
    k_zpq<<<gN8, BN>>>(ew, src, dst, Wg, Ws,
                       (const float4*)Pb, (const float4*)PQb,
                       (float4*)Pa, (float4*)PQa);
    // it2: read A (last: fuse RW + reset deg)
    k_edge_csr<<<gNW, BN>>>(Pa, (const float2*)PQa, D, We, outR, 1);
    k_out<<<gE8, BN>>>(ew, src, dst, (const float4*)Pa, (const float4*)PQa,
                       outX, outXref);
}

// round 7
// speedup vs baseline: 1.2572x; 1.0360x over previous
#include <cuda_runtime.h>
#include <cuda_fp16.h>

#define NN 100000
#define NE 1600000
#define NBLK 391   // ceil(NN/256)

// ---------------- device scratch ----------------
__device__ float        gPa [NN*32];   // P rows fp32, buffer A (src-side loads)
__device__ unsigned int gPQa[NN*32];   // half2{P,Q} rows, buffer A (dst-side gathers)
__device__ float        gPb [NN*32];   // buffer B
__device__ unsigned int gPQb[NN*32];
__device__ float gR [NN*32];
__device__ float gRW[NN*32];
__device__ float gWgT[1024];
__device__ float gWsT[1024];
__device__ float gMg[1024];
__device__ float gMs[1024];
__device__ int   gDeg[NN];      // zero at entry (static init / re-zeroed each call)
__device__ int   gOff[NN];
__device__ int   gOffCur[NN];
__device__ int   gPart[NBLK];
__device__ int   gPartOff[NBLK];
__device__ int2  gEdge[NE];     // {dst, ew_bits}
__device__ int   gEid[NE];      // original edge id (init pass only)

__device__ __forceinline__ float tanha(float x) {
    float y;
    asm("tanh.approx.f32 %0, %1;" : "=f"(y) : "f"(x));
    return y;
}

__device__ __forceinline__ unsigned int packh2(float a, float b) {
    __half2 h = __floats2half2_rn(a, b);
    return *reinterpret_cast<unsigned int*>(&h);
}
__device__ __forceinline__ float2 unpackh2(unsigned int u) {
    __half2 h = *reinterpret_cast<__half2*>(&u);
    return __half22float2(h);
}

// ---------------- prep ----------------
__global__ void k_prep(const float* __restrict__ Wg, const float* __restrict__ Ws,
                       const float* __restrict__ We) {
    int t = threadIdx.x;
    int i = t >> 5, j = t & 31;
    gWgT[t] = Wg[j*32 + i];
    gWsT[t] = Ws[j*32 + i];
    float mg = 0.f, ms = 0.f;
    #pragma unroll
    for (int k = 0; k < 32; k++) {
        float we = We[k*32 + j];
        mg += Wg[k*32 + i] * we;
        ms += Ws[k*32 + i] * we;
    }
    gMg[t] = mg; gMs[t] = ms;
}

// ---------------- CSR build ----------------
__global__ __launch_bounds__(256) void k_hist(const int* __restrict__ src) {
    int e = blockIdx.x * 256 + threadIdx.x;   // NE exact
    atomicAdd(&gDeg[__ldg(src + e)], 1);
}

__global__ __launch_bounds__(256) void k_part() {
    __shared__ int sp[256];
    int t = threadIdx.x;
    int i = blockIdx.x * 256 + t;
    int v = (i < NN) ? gDeg[i] : 0;
    sp[t] = v;
    __syncthreads();
    #pragma unroll
    for (int off = 128; off > 0; off >>= 1) {
        if (t < off) sp[t] += sp[t + off];
        __syncthreads();
    }
    if (t == 0) gPart[blockIdx.x] = sp[0];
}

__global__ void k_top() {
    __shared__ int sp[512];
    int t = threadIdx.x;
    int v = (t < NBLK) ? gPart[t] : 0;
    sp[t] = v;
    __syncthreads();
    #pragma unroll
    for (int off = 1; off < 512; off <<= 1) {
        int u = (t >= off) ? sp[t - off] : 0;
        __syncthreads();
        sp[t] += u;
        __syncthreads();
    }
    if (t < NBLK) gPartOff[t] = sp[t] - v;   // exclusive
}

__global__ __launch_bounds__(256) void k_apply() {
    __shared__ int sp[256];
    int t = threadIdx.x;
    int i = blockIdx.x * 256 + t;
    int v = (i < NN) ? gDeg[i] : 0;
    sp[t] = v;
    __syncthreads();
    #pragma unroll
    for (int off = 1; off < 256; off <<= 1) {
        int u = (t >= off) ? sp[t - off] : 0;
        __syncthreads();
        sp[t] += u;
        __syncthreads();
    }
    if (i < NN) {
        int excl = gPartOff[blockIdx.x] + sp[t] - v;
        gOff[i] = excl;
        gOffCur[i] = excl;
    }
}

__global__ __launch_bounds__(256) void k_scatter(const int* __restrict__ src,
                                                 const int* __restrict__ dst,
                                                 const float* __restrict__ ew) {
    int e = blockIdx.x * 256 + threadIdx.x;   // NE exact
    int s = __ldg(src + e);
    int pos = atomicAdd(&gOffCur[s], 1);
    gEdge[pos] = make_int2(__ldg(dst + e), __float_as_int(__ldg(ew + e)));
    gEid[pos] = e;
}

// ---------------- init: R = D - segsum(xE, src), warp per node ----------------
__global__ __launch_bounds__(256) void k_init_csr(const float* __restrict__ xE,
                                                  const float* __restrict__ D,
                                                  float* __restrict__ outR) {
    int wid = threadIdx.x >> 5, lane = threadIdx.x & 31;
    int n = blockIdx.x * 8 + wid;             // grid = NN/8 exact
    int start = gOff[n], deg = gDeg[n];
    const int* ei = gEid + start;
    float acc = 0.f;
    int j = 0;
    for (; j + 4 <= deg; j += 4) {
        int e0 = __ldg(ei + j),     e1 = __ldg(ei + j + 1);
        int e2 = __ldg(ei + j + 2), e3 = __ldg(ei + j + 3);
        float v0 = __ldg(xE + (size_t)e0 * 32 + lane);
        float v1 = __ldg(xE + (size_t)e1 * 32 + lane);
        float v2 = __ldg(xE + (size_t)e2 * 32 + lane);
        float v3 = __ldg(xE + (size_t)e3 * 32 + lane);
        acc += (v0 + v1) + (v2 + v3);
    }
    for (; j < deg; j++) {
        int e = __ldg(ei + j);
        acc += __ldg(xE + (size_t)e * 32 + lane);
    }
    float r = __ldg(D + n*32 + lane) - acc;
    gR[n*32 + lane] = r;
    outR[n*32 + lane] = r;
}

// ---------------- fused Y0 + P,Q (edge order, e<NN) ----------------
__global__ __launch_bounds__(256) void k_y0pq(const float4* __restrict__ xE4,
                                              const float* __restrict__ ew,
                                              const int* __restrict__ src,
                                              const int* __restrict__ dst,
                                              const float* __restrict__ Wg,
                                              const float* __restrict__ Ws,
                                              float4* __restrict__ Pout,
                                              uint4* __restrict__ PQout) {
    __shared__ float sWg[1024], sWs[1024];
    __shared__ float sY[32][33];
    int t = threadIdx.x;
    for (int i = t; i < 1024; i += 256) { sWg[i] = __ldg(Wg + i); sWs[i] = __ldg(Ws + i); }
    int idx = blockIdx.x * 256 + t;           // NN*8
    int e = idx >> 3, c = idx & 7, el = t >> 3, k0 = c * 4;
    int s = __ldg(src + e), d = __ldg(dst + e);
    float w = __ldg(ew + e);
    float4 x = __ldg(xE4 + idx);
    float4 rs = ((const float4*)gR)[s*8 + c];
    float4 rd = ((const float4*)gR)[d*8 + c];
    sY[el][k0+0] = x.x + w*(rs.x - rd.x);
    sY[el][k0+1] = x.y + w*(rs.y - rd.y);
    sY[el][k0+2] = x.z + w*(rs.z - rd.z);
    sY[el][k0+3] = x.w + w*(rs.w - rd.w);
    __syncthreads();
    float4 p = make_float4(0,0,0,0), q = make_float4(0,0,0,0);
    #pragma unroll
    for (int k = 0; k < 32; k++) {
        float yk = sY[el][k];
        float4 wg = *(const float4*)(sWg + k*32 + k0);
        float4 ws = *(const float4*)(sWs + k*32 + k0);
        p.x += yk*wg.x; p.y += yk*wg.y; p.z += yk*wg.z; p.w += yk*wg.w;
        q.x += yk*ws.x; q.y += yk*ws.y; q.z += yk*ws.z; q.w += yk*ws.w;
    }
    Pout[idx] = p;
    uint4 hp;
    hp.x = packh2(p.x, q.x);
    hp.y = packh2(p.y, q.y);
    hp.z = packh2(p.z, q.z);
    hp.w = packh2(p.w, q.w);
    PQout[idx] = hp;                          // row e = 8 uint4 = 128B
}

// ---------------- main edge pass: warp per node, half2 PQ gather ----------------
__global__ __launch_bounds__(256) void k_edge_csr(const float* __restrict__ P,
                                                  const unsigned int* __restrict__ PQh,
                                                  const float* __restrict__ D,
                                                  const float* __restrict__ We,
                                                  float* __restrict__ outR,
                                                  int last) {
    int wid = threadIdx.x >> 5, lane = threadIdx.x & 31;
    int n = blockIdx.x * 8 + wid;             // grid = NN/8 exact
    float ps = __ldg(P + (size_t)n*32 + lane);
    int start = gOff[n], deg = gDeg[n];
    const int2* ep = gEdge + start;
    float ag = 0.f, as = 0.f;
    int j = 0;
    for (; j + 4 <= deg; j += 4) {
        int2 E0 = __ldg(ep + j);
        int2 E1 = __ldg(ep + j + 1);
        int2 E2 = __ldg(ep + j + 2);
        int2 E3 = __ldg(ep + j + 3);
        unsigned int u0 = __ldg(PQh + (size_t)E0.x * 32 + lane);
        unsigned int u1 = __ldg(PQh + (size_t)E1.x * 32 + lane);
        unsigned int u2 = __ldg(PQh + (size_t)E2.x * 32 + lane);
        unsigned int u3 = __ldg(PQh + (size_t)E3.x * 32 + lane);
        float2 pq0 = unpackh2(u0), pq1 = unpackh2(u1);
        float2 pq2 = unpackh2(u2), pq3 = unpackh2(u3);
        float w0 = __int_as_float(E0.y), w1 = __int_as_float(E1.y);
        float w2 = __int_as_float(E2.y), w3 = __int_as_float(E3.y);
        float tg0 = tanha(w0*(ps-pq0.x)), ts0 = tanha(w0*pq0.y);
        float tg1 = tanha(w1*(ps-pq1.x)), ts1 = tanha(w1*pq1.y);
        float tg2 = tanha(w2*(ps-pq2.x)), ts2 = tanha(w2*pq2.y);
        float tg3 = tanha(w3*(ps-pq3.x)), ts3 = tanha(w3*pq3.y);
        ag += (tg0 + tg1) + (tg2 + tg3);
        as += (ts0 + ts1) + (ts2 + ts3);
    }
    for (; j < deg; j++) {
        int2 E = __ldg(ep + j);
        float w = __int_as_float(E.y);
        float2 pq = unpackh2(__ldg(PQh + (size_t)E.x * 32 + lane));
        ag += tanha(w*(ps-pq.x));
        as += tanha(w*pq.y);
    }
    // epilogue GEMM via warp shuffles
    float acc = 0.f;
    #pragma unroll
    for (int k = 0; k < 32; k++) {
        float a = __shfl_sync(0xffffffffu, ag, k);
        float b = __shfl_sync(0xffffffffu, as, k);
        acc += a * __ldg(gWgT + k*32 + lane) + b * __ldg(gWsT + k*32 + lane);
    }
    float r = __ldg(D + n*32 + lane) - acc;
    gR[n*32 + lane] = r;
    outR[n*32 + lane] = r;
    if (last) {
        // RW = R @ We fused here
        float rw = 0.f;
        #pragma unroll
        for (int k = 0; k < 32; k++) {
            float rk = __shfl_sync(0xffffffffu, r, k);
            rw += rk * __ldg(We + k*32 + lane);
        }
        gRW[n*32 + lane] = rw;
        if (lane == 0) gDeg[n] = 0;   // restore zero invariant for next replay
    }
}

// ---------------- fused Zref + P,Q for next iter: read IN, write OUT ----------------
__global__ __launch_bounds__(256) void k_zpq(const float* __restrict__ ew,
                                             const int* __restrict__ src,
                                             const int* __restrict__ dst,
                                             const float* __restrict__ Wg,
                                             const float* __restrict__ Ws,
                                             const float4* __restrict__ Pin,
                                             const uint4* __restrict__ PQin,
                                             float4* __restrict__ Pout,
                                             uint4* __restrict__ PQout) {
    __shared__ float sWgT[1024], sWsT[1024], sWg[1024], sWs[1024];
    __shared__ float sA[32][33], sB[32][33], sY[32][33];
    int t = threadIdx.x;
    for (int i = t; i < 1024; i += 256) {
        sWgT[i] = gWgT[i]; sWsT[i] = gWsT[i];
        sWg[i] = __ldg(Wg + i); sWs[i] = __ldg(Ws + i);
    }
    int idx = blockIdx.x * 256 + t;           // NN*8
    int e = idx >> 3, c = idx & 7, el = t >> 3, k0 = c * 4;
    int s = __ldg(src + e), d = __ldg(dst + e);
    float w = __ldg(ew + e);
    float4 ps = __ldg(Pin + s*8 + c);
    uint4 hu  = __ldg(PQin + d*8 + c);        // 4 x half2{P,Q} for k0..k0+3
    float2 pq0 = unpackh2(hu.x), pq1 = unpackh2(hu.y);
    float2 pq2 = unpackh2(hu.z), pq3 = unpackh2(hu.w);
    sA[el][k0+0] = tanha(w*(ps.x - pq0.x));
    sA[el][k0+1] = tanha(w*(ps.y - pq1.x));
    sA[el][k0+2] = tanha(w*(ps.z - pq2.x));
    sA[el][k0+3] = tanha(w*(ps.w - pq3.x));
    sB[el][k0+0] = tanha(w*pq0.y);
    sB[el][k0+1] = tanha(w*pq1.y);
    sB[el][k0+2] = tanha(w*pq2.y);
    sB[el][k0+3] = tanha(w*pq3.y);
    float4 rs = ((const float4*)gR)[s*8 + c];
    float4 rd = ((const float4*)gR)[d*8 + c];
    __syncthreads();
    float4 acc;
    acc.x = w*(rs.x-rd.x); acc.y = w*(rs.y-rd.y);
    acc.z = w*(rs.z-rd.z); acc.w = w*(rs.w-rd.w);
    #pragma unroll
    for (int k = 0; k < 32; k++) {
        float ak = sA[el][k], bk = sB[el][k];
        float4 wg = *(const float4*)(sWgT + k*32 + k0);
        float4 ws = *(const float4*)(sWsT + k*32 + k0);
        acc.x += ak*wg.x + bk*ws.x;
        acc.y += ak*wg.y + bk*ws.y;
        acc.z += ak*wg.z + bk*ws.z;
        acc.w += ak*wg.w + bk*ws.w;
    }
    __syncthreads();
    sY[el][k0+0]=acc.x; sY[el][k0+1]=acc.y; sY[el][k0+2]=acc.z; sY[el][k0+3]=acc.w;
    __syncthreads();
    float4 p = make_float4(0,0,0,0), q = make_float4(0,0,0,0);
    #pragma unroll
    for (int k = 0; k < 32; k++) {
        float yk = sY[el][k];
        float4 wg = *(const float4*)(sWg + k*32 + k0);
        float4 ws = *(const float4*)(sWs + k*32 + k0);
        p.x += yk*wg.x; p.y += yk*wg.y; p.z += yk*wg.z; p.w += yk*wg.w;
        q.x += yk*ws.x; q.y += yk*ws.y; q.z += yk*ws.z; q.w += yk*ws.w;
    }
    Pout[idx] = p;
    uint4 hp;
    hp.x = packh2(p.x, q.x);
    hp.y = packh2(p.y, q.y);
    hp.z = packh2(p.z, q.z);
    hp.w = packh2(p.w, q.w);
    PQout[idx] = hp;
}

// ---------------- final outputs (edge order) ----------------
__global__ __launch_bounds__(256) void k_out(const float* __restrict__ ew,
                                             const int* __restrict__ src,
                                             const int* __restrict__ dst,
                                             const float4* __restrict__ Pin,
                                             const uint4* __restrict__ PQin,
                                             float4* __restrict__ outX,
                                             float4* __restrict__ outXref) {
    __shared__ float sMg[1024], sMs[1024];
    __shared__ float stg[32][33], sts[32][33];
    int t = threadIdx.x;
    for (int i = t; i < 1024; i += 256) { sMg[i] = gMg[i]; sMs[i] = gMs[i]; }
    int idx = blockIdx.x * 256 + t;           // NE*8
    int e = idx >> 3, c = idx & 7, el = t >> 3, k0 = c * 4;
    int s = __ldg(src + e), d = __ldg(dst + e);
    float w = __ldg(ew + e);
    float4 ps = __ldg(Pin + s*8 + c);
    uint4 hu  = __ldg(PQin + d*8 + c);
    float2 pq0 = unpackh2(hu.x), pq1 = unpackh2(hu.y);
    float2 pq2 = unpackh2(hu.z), pq3 = unpackh2(hu.w);
    stg[el][k0+0] = tanha(w*(ps.x - pq0.x));
    stg[el][k0+1] = tanha(w*(ps.y - pq1.x));
    stg[el][k0+2] = tanha(w*(ps.z - pq2.x));
    stg[el][k0+3] = tanha(w*(ps.w - pq3.x));
    sts[el][k0+0] = tanha(w*pq0.y);
    sts[el][k0+1] = tanha(w*pq1.y);
    sts[el][k0+2] = tanha(w*pq2.y);
    sts[el][k0+3] = tanha(w*pq3.y);
    __syncthreads();
    float4 xr = make_float4(0,0,0,0);
    #pragma unroll
    for (int k = 0; k < 32; k++) {
        float tgk = stg[el][k], tsk = sts[el][k];
        float4 mg = *(const float4*)(sMg + k*32 + k0);
        float4 ms = *(const float4*)(sMs + k*32 + k0);
        xr.x += tgk*mg.x + tsk*ms.x;
        xr.y += tgk*mg.y + tsk*ms.y;
        xr.z += tgk*mg.z + tsk*ms.z;
        xr.w += tgk*mg.w + tsk*ms.w;
    }
    const float4* RW4 = (const float4*)gRW;
    float4 rs = __ldg(RW4 + s*8 + c);
    float4 rd = __ldg(RW4 + d*8 + c);
    float4 x;
    x.x = xr.x + w*(rs.x-rd.x);
    x.y = xr.y + w*(rs.y-rd.y);
    x.z = xr.z + w*(rs.z-rd.z);
    x.w = xr.w + w*(rs.w-rd.w);
    outX[idx] = x;
    outXref[idx] = xr;
}

// ---------------- launch ----------------
extern "C" void kernel_launch(void* const* d_in, const int* in_sizes, int n_in,
                              void* d_out, int out_size) {
    const float* D  = (const float*)d_in[0];
    const float* xE = (const float*)d_in[1];
    const float* ew = (const float*)d_in[2];
    const float* Wg = (const float*)d_in[3];
    const float* Ws = (const float*)d_in[4];
    const float* We = (const float*)d_in[5];
    const int* eidx = (const int*)d_in[6];
    const int* src = eidx;
    const int* dst = eidx + NE;
    float* out = (float*)d_out;
    float4* outX    = (float4*)out;
    float4* outXref = (float4*)(out + (size_t)NE * 32);
    float*  outR    = out + (size_t)2 * NE * 32;

    // resolve ping-pong buffer addresses (host-side query; capture-safe, no alloc)
    static float *Pa = nullptr, *Pb = nullptr;
    static unsigned int *PQa = nullptr, *PQb = nullptr;
    if (!Pa) {
        cudaGetSymbolAddress((void**)&Pa,  gPa);
        cudaGetSymbolAddress((void**)&PQa, gPQa);
        cudaGetSymbolAddress((void**)&Pb,  gPb);
        cudaGetSymbolAddress((void**)&PQb, gPQb);
    }

    const int BN = 256;
    const int gN8 = NN * 8 / BN;    // 3125
    const int gE8 = NE * 8 / BN;    // 50000
    const int gE  = NE / BN;        // 6250
    const int gNW = NN / 8;         // 12500 (warp per node)

    k_prep<<<1, 1024>>>(Wg, Ws, We);
    k_hist<<<gE, BN>>>(src);
    k_part<<<NBLK, BN>>>();
    k_top<<<1, 512>>>();
    k_apply<<<NBLK, BN>>>();
    k_scatter<<<gE, BN>>>(src, dst, ew);
    k_init_csr<<<gNW, BN>>>(xE, D, outR);
    k_y0pq<<<gN8, BN>>>((const float4*)xE, ew, src, dst, Wg, Ws,
                        (float4*)Pa, (uint4*)PQa);
    // it0: read A; zpq A->B
    k_edge_csr<<<gNW, BN>>>(Pa, PQa, D, We, outR, 0);
    k_zpq<<<gN8, BN>>>(ew, src, dst, Wg, Ws,
                       (const float4*)Pa, (const uint4*)PQa,
                       (float4*)Pb, (uint4*)PQb);
    // it1: read B; zpq B->A
    k_edge_csr<<<gNW, BN>>>(Pb, PQb, D, We, outR, 0);
    k_zpq<<<gN8, BN>>>(ew, src, dst, Wg, Ws,
                       (const float4*)Pb, (const uint4*)PQb,
                       (float4*)Pa, (uint4*)PQa);
    // it2: read A (last: fuse RW + reset deg)
    k_edge_csr<<<gNW, BN>>>(Pa, PQa, D, We, outR, 1);
    k_out<<<gE8, BN>>>(ew, src, dst, (const float4*)Pa, (const uint4*)PQa,
                       outX, outXref);
}

// round 8
// speedup vs baseline: 1.2574x; 1.0002x over previous
#include <cuda_runtime.h>
#include <cuda_fp16.h>

#define NN 100000
#define NE 1600000
#define NBLK 391   // ceil(NN/256)

// ---------------- device scratch ----------------
__device__ float          gPa [NN*32];   // P rows fp32, buffer A (src-side loads in edge pass)
__device__ unsigned int   gPQa[NN*32];   // half2{P,Q} rows, buffer A (gathers)
__device__ float          gPb [NN*32];   // buffer B
__device__ unsigned int   gPQb[NN*32];
__device__ float          gR  [NN*32];
__device__ unsigned short gRWh[NN*32];   // RW in half (k_out gathers)
__device__ float gWgT[1024];
__device__ float gWsT[1024];
__device__ float gMg[1024];
__device__ float gMs[1024];
__device__ int   gDeg[NN];      // zero at entry (static init / re-zeroed each call)
__device__ int   gOff[NN];
__device__ int   gOffCur[NN];
__device__ int   gPart[NBLK];
__device__ int   gPartOff[NBLK];
__device__ int2  gEdge[NE];     // {dst, ew_bits}
__device__ int   gEid[NE];      // original edge id (init pass only)

__device__ __forceinline__ float tanha(float x) {
    float y;
    asm("tanh.approx.f32 %0, %1;" : "=f"(y) : "f"(x));
    return y;
}

__device__ __forceinline__ unsigned int packh2(float a, float b) {
    __half2 h = __floats2half2_rn(a, b);
    return *reinterpret_cast<unsigned int*>(&h);
}
__device__ __forceinline__ float2 unpackh2(unsigned int u) {
    __half2 h = *reinterpret_cast<__half2*>(&u);
    return __half22float2(h);
}

// packed f32x2 helpers (Blackwell FFMA2 via PTX)
__device__ __forceinline__ unsigned long long pk2(float a, float b) {
    unsigned long long r;
    asm("mov.b64 %0, {%1, %2};" : "=l"(r) : "f"(a), "f"(b));
    return r;
}
__device__ __forceinline__ void fma2(unsigned long long& acc,
                                     unsigned long long a, unsigned long long b) {
    asm("fma.rn.f32x2 %0, %1, %2, %0;" : "+l"(acc) : "l"(a), "l"(b));
}
__device__ __forceinline__ float2 upk2(unsigned long long v) {
    float2 f;
    asm("mov.b64 {%0, %1}, %2;" : "=f"(f.x), "=f"(f.y) : "l"(v));
    return f;
}

// ---------------- prep ----------------
__global__ void k_prep(const float* __restrict__ Wg, const float* __restrict__ Ws,
                       const float* __restrict__ We) {
    int t = threadIdx.x;
    int i = t >> 5, j = t & 31;
    gWgT[t] = Wg[j*32 + i];
    gWsT[t] = Ws[j*32 + i];
    float mg = 0.f, ms = 0.f;
    #pragma unroll
    for (int k = 0; k < 32; k++) {
        float we = We[k*32 + j];
        mg += Wg[k*32 + i] * we;
        ms += Ws[k*32 + i] * we;
    }
    gMg[t] = mg; gMs[t] = ms;
}

// ---------------- CSR build ----------------
__global__ __launch_bounds__(256) void k_hist(const int* __restrict__ src) {
    int e = blockIdx.x * 256 + threadIdx.x;   // NE exact
    atomicAdd(&gDeg[__ldg(src + e)], 1);
}

__global__ __launch_bounds__(256) void k_part() {
    __shared__ int sp[256];
    int t = threadIdx.x;
    int i = blockIdx.x * 256 + t;
    int v = (i < NN) ? gDeg[i] : 0;
    sp[t] = v;
    __syncthreads();
    #pragma unroll
    for (int off = 128; off > 0; off >>= 1) {
        if (t < off) sp[t] += sp[t + off];
        __syncthreads();
    }
    if (t == 0) gPart[blockIdx.x] = sp[0];
}

__global__ void k_top() {
    __shared__ int sp[512];
    int t = threadIdx.x;
    int v = (t < NBLK) ? gPart[t] : 0;
    sp[t] = v;
    __syncthreads();
    #pragma unroll
    for (int off = 1; off < 512; off <<= 1) {
        int u = (t >= off) ? sp[t - off] : 0;
        __syncthreads();
        sp[t] += u;
        __syncthreads();
    }
    if (t < NBLK) gPartOff[t] = sp[t] - v;   // exclusive
}

__global__ __launch_bounds__(256) void k_apply() {
    __shared__ int sp[256];
    int t = threadIdx.x;
    int i = blockIdx.x * 256 + t;
    int v = (i < NN) ? gDeg[i] : 0;
    sp[t] = v;
    __syncthreads();
    #pragma unroll
    for (int off = 1; off < 256; off <<= 1) {
        int u = (t >= off) ? sp[t - off] : 0;
        __syncthreads();
        sp[t] += u;
        __syncthreads();
    }
    if (i < NN) {
        int excl = gPartOff[blockIdx.x] + sp[t] - v;
        gOff[i] = excl;
        gOffCur[i] = excl;
    }
}

__global__ __launch_bounds__(256) void k_scatter(const int* __restrict__ src,
                                                 const int* __restrict__ dst,
                                                 const float* __restrict__ ew) {
    int e = blockIdx.x * 256 + threadIdx.x;   // NE exact
    int s = __ldg(src + e);
    int pos = atomicAdd(&gOffCur[s], 1);
    gEdge[pos] = make_int2(__ldg(dst + e), __float_as_int(__ldg(ew + e)));
    gEid[pos] = e;
}

// ---------------- init: R = D - segsum(xE, src), warp per node ----------------
__global__ __launch_bounds__(256) void k_init_csr(const float* __restrict__ xE,
                                                  const float* __restrict__ D,
                                                  float* __restrict__ outR) {
    int wid = threadIdx.x >> 5, lane = threadIdx.x & 31;
    int n = blockIdx.x * 8 + wid;             // grid = NN/8 exact
    int start = gOff[n], deg = gDeg[n];
    const int* ei = gEid + start;
    float acc = 0.f;
    int j = 0;
    for (; j + 8 <= deg; j += 8) {
        int e0 = __ldg(ei + j),     e1 = __ldg(ei + j + 1);
        int e2 = __ldg(ei + j + 2), e3 = __ldg(ei + j + 3);
        int e4 = __ldg(ei + j + 4), e5 = __ldg(ei + j + 5);
        int e6 = __ldg(ei + j + 6), e7 = __ldg(ei + j + 7);
        float v0 = __ldg(xE + (size_t)e0 * 32 + lane);
        float v1 = __ldg(xE + (size_t)e1 * 32 + lane);
        float v2 = __ldg(xE + (size_t)e2 * 32 + lane);
        float v3 = __ldg(xE + (size_t)e3 * 32 + lane);
        float v4 = __ldg(xE + (size_t)e4 * 32 + lane);
        float v5 = __ldg(xE + (size_t)e5 * 32 + lane);
        float v6 = __ldg(xE + (size_t)e6 * 32 + lane);
        float v7 = __ldg(xE + (size_t)e7 * 32 + lane);
        acc += ((v0 + v1) + (v2 + v3)) + ((v4 + v5) + (v6 + v7));
    }
    for (; j < deg; j++) {
        int e = __ldg(ei + j);
        acc += __ldg(xE + (size_t)e * 32 + lane);
    }
    float r = __ldg(D + n*32 + lane) - acc;
    gR[n*32 + lane] = r;
    outR[n*32 + lane] = r;
}

// ---------------- fused Y0 + P,Q (edge order, e<NN) ----------------
__global__ __launch_bounds__(256) void k_y0pq(const float4* __restrict__ xE4,
                                              const float* __restrict__ ew,
                                              const int* __restrict__ src,
                                              const int* __restrict__ dst,
                                              const float* __restrict__ Wg,
                                              const float* __restrict__ Ws,
                                              float4* __restrict__ Pout,
                                              uint4* __restrict__ PQout) {
    __shared__ float sWg[1024], sWs[1024];
    __shared__ float sY[32][33];
    int t = threadIdx.x;
    for (int i = t; i < 1024; i += 256) { sWg[i] = __ldg(Wg + i); sWs[i] = __ldg(Ws + i); }
    int idx = blockIdx.x * 256 + t;           // NN*8
    int e = idx >> 3, c = idx & 7, el = t >> 3, k0 = c * 4;
    int s = __ldg(src + e), d = __ldg(dst + e);
    float w = __ldg(ew + e);
    float4 x = __ldg(xE4 + idx);
    float4 rs = ((const float4*)gR)[s*8 + c];
    float4 rd = ((const float4*)gR)[d*8 + c];
    sY[el][k0+0] = x.x + w*(rs.x - rd.x);
    sY[el][k0+1] = x.y + w*(rs.y - rd.y);
    sY[el][k0+2] = x.z + w*(rs.z - rd.z);
    sY[el][k0+3] = x.w + w*(rs.w - rd.w);
    __syncthreads();
    float4 p = make_float4(0,0,0,0), q = make_float4(0,0,0,0);
    #pragma unroll
    for (int k = 0; k < 32; k++) {
        float yk = sY[el][k];
        float4 wg = *(const float4*)(sWg + k*32 + k0);
        float4 ws = *(const float4*)(sWs + k*32 + k0);
        p.x += yk*wg.x; p.y += yk*wg.y; p.z += yk*wg.z; p.w += yk*wg.w;
        q.x += yk*ws.x; q.y += yk*ws.y; q.z += yk*ws.z; q.w += yk*ws.w;
    }
    Pout[idx] = p;
    uint4 hp;
    hp.x = packh2(p.x, q.x);
    hp.y = packh2(p.y, q.y);
    hp.z = packh2(p.z, q.z);
    hp.w = packh2(p.w, q.w);
    PQout[idx] = hp;                          // row e = 8 uint4 = 128B
}

// ---------------- main edge pass: warp per node, half2 PQ gather, unroll 8 ----------------
__global__ __launch_bounds__(256) void k_edge_csr(const float* __restrict__ P,
                                                  const unsigned int* __restrict__ PQh,
                                                  const float* __restrict__ D,
                                                  const float* __restrict__ We,
                                                  float* __restrict__ outR,
                                                  int last) {
    int wid = threadIdx.x >> 5, lane = threadIdx.x & 31;
    int n = blockIdx.x * 8 + wid;             // grid = NN/8 exact
    float ps = __ldg(P + (size_t)n*32 + lane);
    int start = gOff[n], deg = gDeg[n];
    const int2* ep = gEdge + start;
    float ag = 0.f, as = 0.f;
    int j = 0;
    for (; j + 8 <= deg; j += 8) {
        int2 E0 = __ldg(ep + j);
        int2 E1 = __ldg(ep + j + 1);
        int2 E2 = __ldg(ep + j + 2);
        int2 E3 = __ldg(ep + j + 3);
        int2 E4 = __ldg(ep + j + 4);
        int2 E5 = __ldg(ep + j + 5);
        int2 E6 = __ldg(ep + j + 6);
        int2 E7 = __ldg(ep + j + 7);
        unsigned int u0 = __ldg(PQh + (size_t)E0.x * 32 + lane);
        unsigned int u1 = __ldg(PQh + (size_t)E1.x * 32 + lane);
        unsigned int u2 = __ldg(PQh + (size_t)E2.x * 32 + lane);
        unsigned int u3 = __ldg(PQh + (size_t)E3.x * 32 + lane);
        unsigned int u4 = __ldg(PQh + (size_t)E4.x * 32 + lane);
        unsigned int u5 = __ldg(PQh + (size_t)E5.x * 32 + lane);
        unsigned int u6 = __ldg(PQh + (size_t)E6.x * 32 + lane);
        unsigned int u7 = __ldg(PQh + (size_t)E7.x * 32 + lane);
        float2 pq0 = unpackh2(u0), pq1 = unpackh2(u1);
        float2 pq2 = unpackh2(u2), pq3 = unpackh2(u3);
        float2 pq4 = unpackh2(u4), pq5 = unpackh2(u5);
        float2 pq6 = unpackh2(u6), pq7 = unpackh2(u7);
        float w0 = __int_as_float(E0.y), w1 = __int_as_float(E1.y);
        float w2 = __int_as_float(E2.y), w3 = __int_as_float(E3.y);
        float w4 = __int_as_float(E4.y), w5 = __int_as_float(E5.y);
        float w6 = __int_as_float(E6.y), w7 = __int_as_float(E7.y);
        float a0 = tanha(w0*(ps-pq0.x)), b0 = tanha(w0*pq0.y);
        float a1 = tanha(w1*(ps-pq1.x)), b1 = tanha(w1*pq1.y);
        float a2 = tanha(w2*(ps-pq2.x)), b2 = tanha(w2*pq2.y);
        float a3 = tanha(w3*(ps-pq3.x)), b3 = tanha(w3*pq3.y);
        float a4 = tanha(w4*(ps-pq4.x)), b4 = tanha(w4*pq4.y);
        float a5 = tanha(w5*(ps-pq5.x)), b5 = tanha(w5*pq5.y);
        float a6 = tanha(w6*(ps-pq6.x)), b6 = tanha(w6*pq6.y);
        float a7 = tanha(w7*(ps-pq7.x)), b7 = tanha(w7*pq7.y);
        ag += ((a0+a1)+(a2+a3)) + ((a4+a5)+(a6+a7));
        as += ((b0+b1)+(b2+b3)) + ((b4+b5)+(b6+b7));
    }
    for (; j < deg; j++) {
        int2 E = __ldg(ep + j);
        float w = __int_as_float(E.y);
        float2 pq = unpackh2(__ldg(PQh + (size_t)E.x * 32 + lane));
        ag += tanha(w*(ps-pq.x));
        as += tanha(w*pq.y);
    }
    // epilogue GEMM via warp shuffles
    float acc = 0.f;
    #pragma unroll
    for (int k = 0; k < 32; k++) {
        float a = __shfl_sync(0xffffffffu, ag, k);
        float b = __shfl_sync(0xffffffffu, as, k);
        acc += a * __ldg(gWgT + k*32 + lane) + b * __ldg(gWsT + k*32 + lane);
    }
    float r = __ldg(D + n*32 + lane) - acc;
    gR[n*32 + lane] = r;
    outR[n*32 + lane] = r;
    if (last) {
        // RW = R @ We fused here, stored in half for k_out
        float rw = 0.f;
        #pragma unroll
        for (int k = 0; k < 32; k++) {
            float rk = __shfl_sync(0xffffffffu, r, k);
            rw += rk * __ldg(We + k*32 + lane);
        }
        gRWh[n*32 + lane] = __half_as_ushort(__float2half_rn(rw));
        if (lane == 0) gDeg[n] = 0;   // restore zero invariant for next replay
    }
}

// ---------------- fused Zref + P,Q for next iter: read IN, write OUT ----------------
__global__ __launch_bounds__(256) void k_zpq(const float* __restrict__ ew,
                                             const int* __restrict__ src,
                                             const int* __restrict__ dst,
                                             const float* __restrict__ Wg,
                                             const float* __restrict__ Ws,
                                             const float4* __restrict__ Pin,
                                             const uint4* __restrict__ PQin,
                                             float4* __restrict__ Pout,
                                             uint4* __restrict__ PQout) {
    __shared__ float sWgT[1024], sWsT[1024], sWg[1024], sWs[1024];
    __shared__ float sA[32][33], sB[32][33], sY[32][33];
    int t = threadIdx.x;
    for (int i = t; i < 1024; i += 256) {
        sWgT[i] = gWgT[i]; sWsT[i] = gWsT[i];
        sWg[i] = __ldg(Wg + i); sWs[i] = __ldg(Ws + i);
    }
    int idx = blockIdx.x * 256 + t;           // NN*8
    int e = idx >> 3, c = idx & 7, el = t >> 3, k0 = c * 4;
    int s = __ldg(src + e), d = __ldg(dst + e);
    float w = __ldg(ew + e);
    float4 ps = __ldg(Pin + s*8 + c);
    uint4 hu  = __ldg(PQin + d*8 + c);        // 4 x half2{P,Q} for k0..k0+3
    float2 pq0 = unpackh2(hu.x), pq1 = unpackh2(hu.y);
    float2 pq2 = unpackh2(hu.z), pq3 = unpackh2(hu.w);
    sA[el][k0+0] = tanha(w*(ps.x - pq0.x));
    sA[el][k0+1] = tanha(w*(ps.y - pq1.x));
    sA[el][k0+2] = tanha(w*(ps.z - pq2.x));
    sA[el][k0+3] = tanha(w*(ps.w - pq3.x));
    sB[el][k0+0] = tanha(w*pq0.y);
    sB[el][k0+1] = tanha(w*pq1.y);
    sB[el][k0+2] = tanha(w*pq2.y);
    sB[el][k0+3] = tanha(w*pq3.y);
    float4 rs = ((const float4*)gR)[s*8 + c];
    float4 rd = ((const float4*)gR)[d*8 + c];
    __syncthreads();
    float4 acc;
    acc.x = w*(rs.x-rd.x); acc.y = w*(rs.y-rd.y);
    acc.z = w*(rs.z-rd.z); acc.w = w*(rs.w-rd.w);
    #pragma unroll
    for (int k = 0; k < 32; k++) {
        float ak = sA[el][k], bk = sB[el][k];
        float4 wg = *(const float4*)(sWgT + k*32 + k0);
        float4 ws = *(const float4*)(sWsT + k*32 + k0);
        acc.x += ak*wg.x + bk*ws.x;
        acc.y += ak*wg.y + bk*ws.y;
        acc.z += ak*wg.z + bk*ws.z;
        acc.w += ak*wg.w + bk*ws.w;
    }
    __syncthreads();
    sY[el][k0+0]=acc.x; sY[el][k0+1]=acc.y; sY[el][k0+2]=acc.z; sY[el][k0+3]=acc.w;
    __syncthreads();
    float4 p = make_float4(0,0,0,0), q = make_float4(0,0,0,0);
    #pragma unroll
    for (int k = 0; k < 32; k++) {
        float yk = sY[el][k];
        float4 wg = *(const float4*)(sWg + k*32 + k0);
        float4 ws = *(const float4*)(sWs + k*32 + k0);
        p.x += yk*wg.x; p.y += yk*wg.y; p.z += yk*wg.z; p.w += yk*wg.w;
        q.x += yk*ws.x; q.y += yk*ws.y; q.z += yk*ws.z; q.w += yk*ws.w;
    }
    Pout[idx] = p;
    uint4 hp;
    hp.x = packh2(p.x, q.x);
    hp.y = packh2(p.y, q.y);
    hp.z = packh2(p.z, q.z);
    hp.w = packh2(p.w, q.w);
    PQout[idx] = hp;
}

// ---------------- final outputs (edge order), FFMA2 GEMM, all-half gathers ----------------
__global__ __launch_bounds__(256) void k_out(const float* __restrict__ ew,
                                             const int* __restrict__ src,
                                             const int* __restrict__ dst,
                                             const uint4* __restrict__ PQin,
                                             const unsigned short* __restrict__ RWh,
                                             float4* __restrict__ outX,
                                             float4* __restrict__ outXref) {
    __shared__ float sMg[1024], sMs[1024];
    __shared__ float stg[32][33], sts[32][33];
    int t = threadIdx.x;
    for (int i = t; i < 1024; i += 256) { sMg[i] = gMg[i]; sMs[i] = gMs[i]; }
    int idx = blockIdx.x * 256 + t;           // NE*8
    int e = idx >> 3, c = idx & 7, el = t >> 3, k0 = c * 4;
    int s = __ldg(src + e), d = __ldg(dst + e);
    float w = __ldg(ew + e);
    uint4 hs = __ldg(PQin + s*8 + c);
    uint4 hd = __ldg(PQin + d*8 + c);
    float2 s0 = unpackh2(hs.x), s1 = unpackh2(hs.y), s2 = unpackh2(hs.z), s3 = unpackh2(hs.w);
    float2 d0 = unpackh2(hd.x), d1 = unpackh2(hd.y), d2 = unpackh2(hd.z), d3 = unpackh2(hd.w);
    stg[el][k0+0] = tanha(w*(s0.x - d0.x));
    stg[el][k0+1] = tanha(w*(s1.x - d1.x));
    stg[el][k0+2] = tanha(w*(s2.x - d2.x));
    stg[el][k0+3] = tanha(w*(s3.x - d3.x));
    sts[el][k0+0] = tanha(w*d0.y);
    sts[el][k0+1] = tanha(w*d1.y);
    sts[el][k0+2] = tanha(w*d2.y);
    sts[el][k0+3] = tanha(w*d3.y);
    __syncthreads();
    unsigned long long xr01 = pk2(0.f, 0.f), xr23 = pk2(0.f, 0.f);
    #pragma unroll
    for (int k = 0; k < 32; k++) {
        float tgk = stg[el][k], tsk = sts[el][k];
        unsigned long long tg2 = pk2(tgk, tgk), ts2 = pk2(tsk, tsk);
        const unsigned long long* mg = (const unsigned long long*)(sMg + k*32 + k0);
        const unsigned long long* ms = (const unsigned long long*)(sMs + k*32 + k0);
        fma2(xr01, tg2, mg[0]);
        fma2(xr23, tg2, mg[1]);
        fma2(xr01, ts2, ms[0]);
        fma2(xr23, ts2, ms[1]);
    }
    float2 x01 = upk2(xr01), x23 = upk2(xr23);
    float4 xr = make_float4(x01.x, x01.y, x23.x, x23.y);
    // RW gathers (half, 8B per thread)
    uint2 rs2 = __ldg((const uint2*)(RWh + (size_t)s*32) + c);
    uint2 rd2 = __ldg((const uint2*)(RWh + (size_t)d*32) + c);
    float2 ra0 = unpackh2(rs2.x), ra1 = unpackh2(rs2.y);
    float2 rb0 = unpackh2(rd2.x), rb1 = unpackh2(rd2.y);
    float4 x;
    x.x = xr.x + w*(ra0.x - rb0.x);
    x.y = xr.y + w*(ra0.y - rb0.y);
    x.z = xr.z + w*(ra1.x - rb1.x);
    x.w = xr.w + w*(ra1.y - rb1.y);
    outX[idx] = x;
    outXref[idx] = xr;
}

// ---------------- launch ----------------
extern "C" void kernel_launch(void* const* d_in, const int* in_sizes, int n_in,
                              void* d_out, int out_size) {
    const float* D  = (const float*)d_in[0];
    const float* xE = (const float*)d_in[1];
    const float* ew = (const float*)d_in[2];
    const float* Wg = (const float*)d_in[3];
    const float* Ws = (const float*)d_in[4];
    const float* We = (const float*)d_in[5];
    const int* eidx = (const int*)d_in[6];
    const int* src = eidx;
    const int* dst = eidx + NE;
    float* out = (float*)d_out;
    float4* outX    = (float4*)out;
    float4* outXref = (float4*)(out + (size_t)NE * 32);
    float*  outR    = out + (size_t)2 * NE * 32;

    // resolve ping-pong buffer addresses (host-side query; capture-safe, no alloc)
    static float *Pa = nullptr, *Pb = nullptr;
    static unsigned int *PQa = nullptr, *PQb = nullptr;
    static unsigned short *RWh = nullptr;
    if (!Pa) {
        cudaGetSymbolAddress((void**)&Pa,  gPa);
        cudaGetSymbolAddress((void**)&PQa, gPQa);
        cudaGetSymbolAddress((void**)&Pb,  gPb);
        cudaGetSymbolAddress((void**)&PQb, gPQb);
        cudaGetSymbolAddress((void**)&RWh, gRWh);
    }

    const int BN = 256;
    const int gN8 = NN * 8 / BN;    // 3125
    const int gE8 = NE * 8 / BN;    // 50000
    const int gE  = NE / BN;        // 6250
    const int gNW = NN / 8;         // 12500 (warp per node)

    k_prep<<<1, 1024>>>(Wg, Ws, We);
    k_hist<<<gE, BN>>>(src);
    k_part<<<NBLK, BN>>>();
    k_top<<<1, 512>>>();
    k_apply<<<NBLK, BN>>>();
    k_scatter<<<gE, BN>>>(src, dst, ew);
    k_init_csr<<<gNW, BN>>>(xE, D, outR);
    k_y0pq<<<gN8, BN>>>((const float4*)xE, ew, src, dst, Wg, Ws,
                        (float4*)Pa, (uint4*)PQa);
    // it0: read A; zpq A->B
    k_edge_csr<<<gNW, BN>>>(Pa, PQa, D, We, outR, 0);
    k_zpq<<<gN8, BN>>>(ew, src, dst, Wg, Ws,
                       (const float4*)Pa, (const uint4*)PQa,
                       (float4*)Pb, (uint4*)PQb);
    // it1: read B; zpq B->A
    k_edge_csr<<<gNW, BN>>>(Pb, PQb, D, We, outR, 0);
    k_zpq<<<gN8, BN>>>(ew, src, dst, Wg, Ws,
                       (const float4*)Pb, (const uint4*)PQb,
                       (float4*)Pa, (uint4*)PQa);
    // it2: read A (last: fuse RW(half) + reset deg)
    k_edge_csr<<<gNW, BN>>>(Pa, PQa, D, We, outR, 1);
    k_out<<<gE8, BN>>>(ew, src, dst, (const uint4*)PQa, RWh, outX, outXref);
}

// round 9
// speedup vs baseline: 1.8440x; 1.4665x over previous
#include <cuda_runtime.h>
#include <cuda_fp16.h>

#define NN 100000
#define NE 1600000
#define NBLK 391   // ceil(NN/256)

// ---------------- device scratch ----------------
__device__ float          gPa [NN*32];   // P rows fp32, buffer A (src-side loads in edge pass)
__device__ unsigned int   gPQa[NN*32];   // half2{P,Q} rows, buffer A (gathers)
__device__ float          gPb [NN*32];   // buffer B
__device__ unsigned int   gPQb[NN*32];
__device__ float          gR  [NN*32];
__device__ unsigned short gRWh[NN*32];   // RW in half (k_out gathers)
__device__ float gWgT[1024];
__device__ float gWsT[1024];
__device__ float gMg[1024];
__device__ float gMs[1024];
__device__ int   gDeg[NN];      // zero at entry (static init / re-zeroed each call)
__device__ int   gOff[NN];
__device__ int   gOffCur[NN];
__device__ int   gPart[NBLK];
__device__ int   gPartOff[NBLK];
__device__ int2  gEdge[NE];     // {dst, ew_bits}
__device__ int   gEid[NE];      // original edge id (init pass only)

__device__ __forceinline__ float tanha(float x) {
    float y;
    asm("tanh.approx.f32 %0, %1;" : "=f"(y) : "f"(x));
    return y;
}

__device__ __forceinline__ unsigned int packh2(float a, float b) {
    __half2 h = __floats2half2_rn(a, b);
    return *reinterpret_cast<unsigned int*>(&h);
}
__device__ __forceinline__ float2 unpackh2(unsigned int u) {
    __half2 h = *reinterpret_cast<__half2*>(&u);
    return __half22float2(h);
}

__device__ __forceinline__ unsigned int tf32r(float x) {
    unsigned int r;
    asm("cvt.rna.tf32.f32 %0, %1;" : "=r"(r) : "f"(x));
    return r;
}

// ---------------- prep ----------------
__global__ void k_prep(const float* __restrict__ Wg, const float* __restrict__ Ws,
                       const float* __restrict__ We) {
    int t = threadIdx.x;
    int i = t >> 5, j = t & 31;
    gWgT[t] = Wg[j*32 + i];
    gWsT[t] = Ws[j*32 + i];
    float mg = 0.f, ms = 0.f;
    #pragma unroll
    for (int k = 0; k < 32; k++) {
        float we = We[k*32 + j];
        mg += Wg[k*32 + i] * we;
        ms += Ws[k*32 + i] * we;
    }
    gMg[t] = mg; gMs[t] = ms;
}

// ---------------- CSR build ----------------
__global__ __launch_bounds__(256) void k_hist(const int* __restrict__ src) {
    int e = blockIdx.x * 256 + threadIdx.x;   // NE exact
    atomicAdd(&gDeg[__ldg(src + e)], 1);
}

__global__ __launch_bounds__(256) void k_part() {
    __shared__ int sp[256];
    int t = threadIdx.x;
    int i = blockIdx.x * 256 + t;
    int v = (i < NN) ? gDeg[i] : 0;
    sp[t] = v;
    __syncthreads();
    #pragma unroll
    for (int off = 128; off > 0; off >>= 1) {
        if (t < off) sp[t] += sp[t + off];
        __syncthreads();
    }
    if (t == 0) gPart[blockIdx.x] = sp[0];
}

__global__ void k_top() {
    __shared__ int sp[512];
    int t = threadIdx.x;
    int v = (t < NBLK) ? gPart[t] : 0;
    sp[t] = v;
    __syncthreads();
    #pragma unroll
    for (int off = 1; off < 512; off <<= 1) {
        int u = (t >= off) ? sp[t - off] : 0;
        __syncthreads();
        sp[t] += u;
        __syncthreads();
    }
    if (t < NBLK) gPartOff[t] = sp[t] - v;   // exclusive
}

__global__ __launch_bounds__(256) void k_apply() {
    __shared__ int sp[256];
    int t = threadIdx.x;
    int i = blockIdx.x * 256 + t;
    int v = (i < NN) ? gDeg[i] : 0;
    sp[t] = v;
    __syncthreads();
    #pragma unroll
    for (int off = 1; off < 256; off <<= 1) {
        int u = (t >= off) ? sp[t - off] : 0;
        __syncthreads();
        sp[t] += u;
        __syncthreads();
    }
    if (i < NN) {
        int excl = gPartOff[blockIdx.x] + sp[t] - v;
        gOff[i] = excl;
        gOffCur[i] = excl;
    }
}

__global__ __launch_bounds__(256) void k_scatter(const int* __restrict__ src,
                                                 const int* __restrict__ dst,
                                                 const float* __restrict__ ew) {
    int e = blockIdx.x * 256 + threadIdx.x;   // NE exact
    int s = __ldg(src + e);
    int pos = atomicAdd(&gOffCur[s], 1);
    gEdge[pos] = make_int2(__ldg(dst + e), __float_as_int(__ldg(ew + e)));
    gEid[pos] = e;
}

// ---------------- init: R = D - segsum(xE, src), warp per node ----------------
__global__ __launch_bounds__(256) void k_init_csr(const float* __restrict__ xE,
                                                  const float* __restrict__ D,
                                                  float* __restrict__ outR) {
    int wid = threadIdx.x >> 5, lane = threadIdx.x & 31;
    int n = blockIdx.x * 8 + wid;             // grid = NN/8 exact
    int start = gOff[n], deg = gDeg[n];
    const int* ei = gEid + start;
    float acc = 0.f;
    int j = 0;
    for (; j + 8 <= deg; j += 8) {
        int e0 = __ldg(ei + j),     e1 = __ldg(ei + j + 1);
        int e2 = __ldg(ei + j + 2), e3 = __ldg(ei + j + 3);
        int e4 = __ldg(ei + j + 4), e5 = __ldg(ei + j + 5);
        int e6 = __ldg(ei + j + 6), e7 = __ldg(ei + j + 7);
        float v0 = __ldg(xE + (size_t)e0 * 32 + lane);
        float v1 = __ldg(xE + (size_t)e1 * 32 + lane);
        float v2 = __ldg(xE + (size_t)e2 * 32 + lane);
        float v3 = __ldg(xE + (size_t)e3 * 32 + lane);
        float v4 = __ldg(xE + (size_t)e4 * 32 + lane);
        float v5 = __ldg(xE + (size_t)e5 * 32 + lane);
        float v6 = __ldg(xE + (size_t)e6 * 32 + lane);
        float v7 = __ldg(xE + (size_t)e7 * 32 + lane);
        acc += ((v0 + v1) + (v2 + v3)) + ((v4 + v5) + (v6 + v7));
    }
    for (; j < deg; j++) {
        int e = __ldg(ei + j);
        acc += __ldg(xE + (size_t)e * 32 + lane);
    }
    float r = __ldg(D + n*32 + lane) - acc;
    gR[n*32 + lane] = r;
    outR[n*32 + lane] = r;
}

// ---------------- fused Y0 + P,Q (edge order, e<NN) ----------------
__global__ __launch_bounds__(256) void k_y0pq(const float4* __restrict__ xE4,
                                              const float* __restrict__ ew,
                                              const int* __restrict__ src,
                                              const int* __restrict__ dst,
                                              const float* __restrict__ Wg,
                                              const float* __restrict__ Ws,
                                              float4* __restrict__ Pout,
                                              uint4* __restrict__ PQout) {
    __shared__ float sWg[1024], sWs[1024];
    __shared__ float sY[32][33];
    int t = threadIdx.x;
    for (int i = t; i < 1024; i += 256) { sWg[i] = __ldg(Wg + i); sWs[i] = __ldg(Ws + i); }
    int idx = blockIdx.x * 256 + t;           // NN*8
    int e = idx >> 3, c = idx & 7, el = t >> 3, k0 = c * 4;
    int s = __ldg(src + e), d = __ldg(dst + e);
    float w = __ldg(ew + e);
    float4 x = __ldg(xE4 + idx);
    float4 rs = ((const float4*)gR)[s*8 + c];
    float4 rd = ((const float4*)gR)[d*8 + c];
    sY[el][k0+0] = x.x + w*(rs.x - rd.x);
    sY[el][k0+1] = x.y + w*(rs.y - rd.y);
    sY[el][k0+2] = x.z + w*(rs.z - rd.z);
    sY[el][k0+3] = x.w + w*(rs.w - rd.w);
    __syncthreads();
    float4 p = make_float4(0,0,0,0), q = make_float4(0,0,0,0);
    #pragma unroll
    for (int k = 0; k < 32; k++) {
        float yk = sY[el][k];
        float4 wg = *(const float4*)(sWg + k*32 + k0);
        float4 ws = *(const float4*)(sWs + k*32 + k0);
        p.x += yk*wg.x; p.y += yk*wg.y; p.z += yk*wg.z; p.w += yk*wg.w;
        q.x += yk*ws.x; q.y += yk*ws.y; q.z += yk*ws.z; q.w += yk*ws.w;
    }
    Pout[idx] = p;
    uint4 hp;
    hp.x = packh2(p.x, q.x);
    hp.y = packh2(p.y, q.y);
    hp.z = packh2(p.z, q.z);
    hp.w = packh2(p.w, q.w);
    PQout[idx] = hp;                          // row e = 8 uint4 = 128B
}

// ---------------- main edge pass: warp per node, half2 PQ gather, unroll 8 ----------------
__global__ __launch_bounds__(256) void k_edge_csr(const float* __restrict__ P,
                                                  const unsigned int* __restrict__ PQh,
                                                  const float* __restrict__ D,
                                                  const float* __restrict__ We,
                                                  float* __restrict__ outR,
                                                  int last) {
    int wid = threadIdx.x >> 5, lane = threadIdx.x & 31;
    int n = blockIdx.x * 8 + wid;             // grid = NN/8 exact
    float ps = __ldg(P + (size_t)n*32 + lane);
    int start = gOff[n], deg = gDeg[n];
    const int2* ep = gEdge + start;
    float ag = 0.f, as = 0.f;
    int j = 0;
    for (; j + 8 <= deg; j += 8) {
        int2 E0 = __ldg(ep + j);
        int2 E1 = __ldg(ep + j + 1);
        int2 E2 = __ldg(ep + j + 2);
        int2 E3 = __ldg(ep + j + 3);
        int2 E4 = __ldg(ep + j + 4);
        int2 E5 = __ldg(ep + j + 5);
        int2 E6 = __ldg(ep + j + 6);
        int2 E7 = __ldg(ep + j + 7);
        unsigned int u0 = __ldg(PQh + (size_t)E0.x * 32 + lane);
        unsigned int u1 = __ldg(PQh + (size_t)E1.x * 32 + lane);
        unsigned int u2 = __ldg(PQh + (size_t)E2.x * 32 + lane);
        unsigned int u3 = __ldg(PQh + (size_t)E3.x * 32 + lane);
        unsigned int u4 = __ldg(PQh + (size_t)E4.x * 32 + lane);
        unsigned int u5 = __ldg(PQh + (size_t)E5.x * 32 + lane);
        unsigned int u6 = __ldg(PQh + (size_t)E6.x * 32 + lane);
        unsigned int u7 = __ldg(PQh + (size_t)E7.x * 32 + lane);
        float2 pq0 = unpackh2(u0), pq1 = unpackh2(u1);
        float2 pq2 = unpackh2(u2), pq3 = unpackh2(u3);
        float2 pq4 = unpackh2(u4), pq5 = unpackh2(u5);
        float2 pq6 = unpackh2(u6), pq7 = unpackh2(u7);
        float w0 = __int_as_float(E0.y), w1 = __int_as_float(E1.y);
        float w2 = __int_as_float(E2.y), w3 = __int_as_float(E3.y);
        float w4 = __int_as_float(E4.y), w5 = __int_as_float(E5.y);
        float w6 = __int_as_float(E6.y), w7 = __int_as_float(E7.y);
        float a0 = tanha(w0*(ps-pq0.x)), b0 = tanha(w0*pq0.y);
        float a1 = tanha(w1*(ps-pq1.x)), b1 = tanha(w1*pq1.y);
        float a2 = tanha(w2*(ps-pq2.x)), b2 = tanha(w2*pq2.y);
        float a3 = tanha(w3*(ps-pq3.x)), b3 = tanha(w3*pq3.y);
        float a4 = tanha(w4*(ps-pq4.x)), b4 = tanha(w4*pq4.y);
        float a5 = tanha(w5*(ps-pq5.x)), b5 = tanha(w5*pq5.y);
        float a6 = tanha(w6*(ps-pq6.x)), b6 = tanha(w6*pq6.y);
        float a7 = tanha(w7*(ps-pq7.x)), b7 = tanha(w7*pq7.y);
        ag += ((a0+a1)+(a2+a3)) + ((a4+a5)+(a6+a7));
        as += ((b0+b1)+(b2+b3)) + ((b4+b5)+(b6+b7));
    }
    for (; j < deg; j++) {
        int2 E = __ldg(ep + j);
        float w = __int_as_float(E.y);
        float2 pq = unpackh2(__ldg(PQh + (size_t)E.x * 32 + lane));
        ag += tanha(w*(ps-pq.x));
        as += tanha(w*pq.y);
    }
    // epilogue GEMM via warp shuffles
    float acc = 0.f;
    #pragma unroll
    for (int k = 0; k < 32; k++) {
        float a = __shfl_sync(0xffffffffu, ag, k);
        float b = __shfl_sync(0xffffffffu, as, k);
        acc += a * __ldg(gWgT + k*32 + lane) + b * __ldg(gWsT + k*32 + lane);
    }
    float r = __ldg(D + n*32 + lane) - acc;
    gR[n*32 + lane] = r;
    outR[n*32 + lane] = r;
    if (last) {
        // RW = R @ We fused here, stored in half for k_out
        float rw = 0.f;
        #pragma unroll
        for (int k = 0; k < 32; k++) {
            float rk = __shfl_sync(0xffffffffu, r, k);
            rw += rk * __ldg(We + k*32 + lane);
        }
        gRWh[n*32 + lane] = __half_as_ushort(__float2half_rn(rw));
        if (lane == 0) gDeg[n] = 0;   // restore zero invariant for next replay
    }
}

// ---------------- fused Zref + P,Q for next iter: read IN, write OUT ----------------
__global__ __launch_bounds__(256) void k_zpq(const float* __restrict__ ew,
                                             const int* __restrict__ src,
                                             const int* __restrict__ dst,
                                             const float* __restrict__ Wg,
                                             const float* __restrict__ Ws,
                                             const float4* __restrict__ Pin,
                                             const uint4* __restrict__ PQin,
                                             float4* __restrict__ Pout,
                                             uint4* __restrict__ PQout) {
    __shared__ float sWgT[1024], sWsT[1024], sWg[1024], sWs[1024];
    __shared__ float sA[32][33], sB[32][33], sY[32][33];
    int t = threadIdx.x;
    for (int i = t; i < 1024; i += 256) {
        sWgT[i] = gWgT[i]; sWsT[i] = gWsT[i];
        sWg[i] = __ldg(Wg + i); sWs[i] = __ldg(Ws + i);
    }
    int idx = blockIdx.x * 256 + t;           // NN*8
    int e = idx >> 3, c = idx & 7, el = t >> 3, k0 = c * 4;
    int s = __ldg(src + e), d = __ldg(dst + e);
    float w = __ldg(ew + e);
    float4 ps = __ldg(Pin + s*8 + c);
    uint4 hu  = __ldg(PQin + d*8 + c);        // 4 x half2{P,Q} for k0..k0+3
    float2 pq0 = unpackh2(hu.x), pq1 = unpackh2(hu.y);
    float2 pq2 = unpackh2(hu.z), pq3 = unpackh2(hu.w);
    sA[el][k0+0] = tanha(w*(ps.x - pq0.x));
    sA[el][k0+1] = tanha(w*(ps.y - pq1.x));
    sA[el][k0+2] = tanha(w*(ps.z - pq2.x));
    sA[el][k0+3] = tanha(w*(ps.w - pq3.x));
    sB[el][k0+0] = tanha(w*pq0.y);
    sB[el][k0+1] = tanha(w*pq1.y);
    sB[el][k0+2] = tanha(w*pq2.y);
    sB[el][k0+3] = tanha(w*pq3.y);
    float4 rs = ((const float4*)gR)[s*8 + c];
    float4 rd = ((const float4*)gR)[d*8 + c];
    __syncthreads();
    float4 acc;
    acc.x = w*(rs.x-rd.x); acc.y = w*(rs.y-rd.y);
    acc.z = w*(rs.z-rd.z); acc.w = w*(rs.w-rd.w);
    #pragma unroll
    for (int k = 0; k < 32; k++) {
        float ak = sA[el][k], bk = sB[el][k];
        float4 wg = *(const float4*)(sWgT + k*32 + k0);
        float4 ws = *(const float4*)(sWsT + k*32 + k0);
        acc.x += ak*wg.x + bk*ws.x;
        acc.y += ak*wg.y + bk*ws.y;
        acc.z += ak*wg.z + bk*ws.z;
        acc.w += ak*wg.w + bk*ws.w;
    }
    __syncthreads();
    sY[el][k0+0]=acc.x; sY[el][k0+1]=acc.y; sY[el][k0+2]=acc.z; sY[el][k0+3]=acc.w;
    __syncthreads();
    float4 p = make_float4(0,0,0,0), q = make_float4(0,0,0,0);
    #pragma unroll
    for (int k = 0; k < 32; k++) {
        float yk = sY[el][k];
        float4 wg = *(const float4*)(sWg + k*32 + k0);
        float4 ws = *(const float4*)(sWs + k*32 + k0);
        p.x += yk*wg.x; p.y += yk*wg.y; p.z += yk*wg.z; p.w += yk*wg.w;
        q.x += yk*ws.x; q.y += yk*ws.y; q.z += yk*ws.z; q.w += yk*ws.w;
    }
    Pout[idx] = p;
    uint4 hp;
    hp.x = packh2(p.x, q.x);
    hp.y = packh2(p.y, q.y);
    hp.z = packh2(p.z, q.z);
    hp.w = packh2(p.w, q.w);
    PQout[idx] = hp;
}

// ---------------- final outputs: tensor-core (mma.sync tf32) Xref GEMM ----------------
// Block = 128 edges, 256 threads = 8 warps. Warp w owns edges [w*16, w*16+16).
// Xref[128x32] = T[128x64] @ M[64x32], T = [tanh_g | tanh_s] (tf32), M = [Mg; Ms] (tf32).
__global__ __launch_bounds__(256) void k_out(const float* __restrict__ ew,
                                             const int* __restrict__ src,
                                             const int* __restrict__ dst,
                                             const uint4* __restrict__ PQin,
                                             const unsigned short* __restrict__ RWh,
                                             float4* __restrict__ outX,
                                             float4* __restrict__ outXref) {
    __shared__ float sT[128 * 68];     // T tile, tf32 bits; row stride 68 (bank-friendly)
    __shared__ float sM[64 * 40];      // M tile, tf32 bits; row stride 40 (conflict-free B frags)
    __shared__ int   sSDW[128 * 3];    // per-edge {src, dst, ew_bits}
    float* sOut = sT;                  // overlay: [128][36] result tile (after MMA reads done)

    int t = threadIdx.x;
    int lane = t & 31, w = t >> 5;

    // load M = [Mg; Ms] as tf32
    for (int i = t; i < 2048; i += 256) {
        int k = i >> 5, n = i & 31;
        float v = (k < 32) ? gMg[k*32 + n] : gMs[(k-32)*32 + n];
        *(unsigned int*)(sM + k*40 + n) = tf32r(v);
    }

    // stage 1: gathers + tanh -> sT (tf32 bits)
    int ebase = blockIdx.x * 128;
    #pragma unroll
    for (int r = 0; r < 4; r++) {
        int el = r*32 + (t >> 3);
        int c  = t & 7;
        int e  = ebase + el;
        int s = __ldg(src + e), d = __ldg(dst + e);
        float wgt = __ldg(ew + e);
        if (c == 0) {
            sSDW[el*3 + 0] = s;
            sSDW[el*3 + 1] = d;
            sSDW[el*3 + 2] = __float_as_int(wgt);
        }
        uint4 hs = __ldg(PQin + s*8 + c);
        uint4 hd = __ldg(PQin + d*8 + c);
        float2 s0 = unpackh2(hs.x), s1 = unpackh2(hs.y), s2 = unpackh2(hs.z), s3 = unpackh2(hs.w);
        float2 d0 = unpackh2(hd.x), d1 = unpackh2(hd.y), d2 = unpackh2(hd.z), d3 = unpackh2(hd.w);
        uint4 tg, ts;
        tg.x = tf32r(tanha(wgt*(s0.x - d0.x)));
        tg.y = tf32r(tanha(wgt*(s1.x - d1.x)));
        tg.z = tf32r(tanha(wgt*(s2.x - d2.x)));
        tg.w = tf32r(tanha(wgt*(s3.x - d3.x)));
        ts.x = tf32r(tanha(wgt*d0.y));
        ts.y = tf32r(tanha(wgt*d1.y));
        ts.z = tf32r(tanha(wgt*d2.y));
        ts.w = tf32r(tanha(wgt*d3.y));
        *(uint4*)(sT + el*68 + c*4)      = tg;   // cols 0..31  = tanh_g
        *(uint4*)(sT + el*68 + 32 + c*4) = ts;   // cols 32..63 = tanh_s
    }
    __syncthreads();

    // stage 2: MMA. D[16x32] per warp: 4 n-tiles of m16n8, K=64 in 16 k4-steps.
    float dacc[4][4];
    #pragma unroll
    for (int nt = 0; nt < 4; nt++)
        #pragma unroll
        for (int i = 0; i < 4; i++) dacc[nt][i] = 0.f;

    int g = lane >> 2;          // 0..7 (row group)
    int tc = lane & 3;          // 0..3
    const float* aRow0 = sT + (w*16 + g)     * 68;
    const float* aRow1 = sT + (w*16 + g + 8) * 68;
    #pragma unroll
    for (int kk = 0; kk < 16; kk++) {
        int k0 = kk * 4;
        unsigned int a0 = *(const unsigned int*)(aRow0 + k0 + tc);
        unsigned int a1 = *(const unsigned int*)(aRow1 + k0 + tc);
        #pragma unroll
        for (int nt = 0; nt < 4; nt++) {
            unsigned int b0 = *(const unsigned int*)(sM + (k0 + tc)*40 + nt*8 + g);
            asm("mma.sync.aligned.m16n8k4.row.col.f32.tf32.tf32.f32 "
                "{%0,%1,%2,%3}, {%4,%5}, {%6}, {%0,%1,%2,%3};"
                : "+f"(dacc[nt][0]), "+f"(dacc[nt][1]),
                  "+f"(dacc[nt][2]), "+f"(dacc[nt][3])
                : "r"(a0), "r"(a1), "r"(b0));
        }
    }
    __syncthreads();   // all warps done reading sT -> safe to overlay sOut

    // store D to sOut[128][36]: d0,d1 at (row g, col 2*tc+{0,1}+nt*8); d2,d3 at row g+8
    #pragma unroll
    for (int nt = 0; nt < 4; nt++) {
        int col = nt*8 + tc*2;
        *(float2*)(sOut + (w*16 + g)*36 + col)     = make_float2(dacc[nt][0], dacc[nt][1]);
        *(float2*)(sOut + (w*16 + g + 8)*36 + col) = make_float2(dacc[nt][2], dacc[nt][3]);
    }
    __syncthreads();

    // stage 3: X = Xref + w*(RW[s]-RW[d]); write outputs
    #pragma unroll
    for (int r = 0; r < 4; r++) {
        int el = r*32 + (t >> 3);
        int c  = t & 7;
        int e  = ebase + el;
        int s = sSDW[el*3 + 0];
        int d = sSDW[el*3 + 1];
        float wgt = __int_as_float(sSDW[el*3 + 2]);
        float4 xr = *(const float4*)(sOut + el*36 + c*4);
        uint2 rs2 = __ldg((const uint2*)(RWh + (size_t)s*32) + c);
        uint2 rd2 = __ldg((const uint2*)(RWh + (size_t)d*32) + c);
        float2 ra0 = unpackh2(rs2.x), ra1 = unpackh2(rs2.y);
        float2 rb0 = unpackh2(rd2.x), rb1 = unpackh2(rd2.y);
        float4 x;
        x.x = xr.x + wgt*(ra0.x - rb0.x);
        x.y = xr.y + wgt*(ra0.y - rb0.y);
        x.z = xr.z + wgt*(ra1.x - rb1.x);
        x.w = xr.w + wgt*(ra1.y - rb1.y);
        outX[(size_t)e*8 + c]    = x;
        outXref[(size_t)e*8 + c] = xr;
    }
}

// ---------------- launch ----------------
extern "C" void kernel_launch(void* const* d_in, const int* in_sizes, int n_in,
                              void* d_out, int out_size) {
    const float* D  = (const float*)d_in[0];
    const float* xE = (const float*)d_in[1];
    const float* ew = (const float*)d_in[2];
    const float* Wg = (const float*)d_in[3];
    const float* Ws = (const float*)d_in[4];
    const float* We = (const float*)d_in[5];
    const int* eidx = (const int*)d_in[6];
    const int* src = eidx;
    const int* dst = eidx + NE;
    float* out = (float*)d_out;
    float4* outX    = (float4*)out;
    float4* outXref = (float4*)(out + (size_t)NE * 32);
    float*  outR    = out + (size_t)2 * NE * 32;

    // resolve ping-pong buffer addresses (host-side query; capture-safe, no alloc)
    static float *Pa = nullptr, *Pb = nullptr;
    static unsigned int *PQa = nullptr, *PQb = nullptr;
    static unsigned short *RWh = nullptr;
    if (!Pa) {
        cudaGetSymbolAddress((void**)&Pa,  gPa);
        cudaGetSymbolAddress((void**)&PQa, gPQa);
        cudaGetSymbolAddress((void**)&Pb,  gPb);
        cudaGetSymbolAddress((void**)&PQb, gPQb);
        cudaGetSymbolAddress((void**)&RWh, gRWh);
    }

    const int BN = 256;
    const int gN8 = NN * 8 / BN;    // 3125
    const int gE  = NE / BN;        // 6250
    const int gNW = NN / 8;         // 12500 (warp per node)
    const int gEO = NE / 128;       // 12500 (k_out: 128 edges per block)

    k_prep<<<1, 1024>>>(Wg, Ws, We);
    k_hist<<<gE, BN>>>(src);
    k_part<<<NBLK, BN>>>();
    k_top<<<1, 512>>>();
    k_apply<<<NBLK, BN>>>();
    k_scatter<<<gE, BN>>>(src, dst, ew);
    k_init_csr<<<gNW, BN>>>(xE, D, outR);
    k_y0pq<<<gN8, BN>>>((const float4*)xE, ew, src, dst, Wg, Ws,
                        (float4*)Pa, (uint4*)PQa);
    // it0: read A; zpq A->B
    k_edge_csr<<<gNW, BN>>>(Pa, PQa, D, We, outR, 0);
    k_zpq<<<gN8, BN>>>(ew, src, dst, Wg, Ws,
                       (const float4*)Pa, (const uint4*)PQa,
                       (float4*)Pb, (uint4*)PQb);
    // it1: read B; zpq B->A
    k_edge_csr<<<gNW, BN>>>(Pb, PQb, D, We, outR, 0);
    k_zpq<<<gN8, BN>>>(ew, src, dst, Wg, Ws,
                       (const float4*)Pb, (const uint4*)PQb,
                       (float4*)Pa, (uint4*)PQa);
    // it2: read A (last: fuse RW(half) + reset deg)
    k_edge_csr<<<gNW, BN>>>(Pa, PQa, D, We, outR, 1);
    k_out<<<gEO, BN>>>(ew, src, dst, (const uint4*)PQa, RWh, outX, outXref);
}